// round 1
// baseline (speedup 1.0000x reference)
#include <cuda_runtime.h>
#include <math.h>

#define NN 50000
#define NE 640000
#define D 128

// ---------------- scratch (device globals; no cudaMalloc allowed) ----------------
__device__ float g_Qh[NN * D];
__device__ float g_Kh[NN * D];
__device__ float g_Vh[NN * D];
__device__ float g_wV[NN * D];
__device__ float g_z[NN * 8];
__device__ float g_hh[NN * D];
__device__ float g_h2[NN * D];
__device__ float g_ee[NE * D];          // 327 MB: ee_pre (post Wo_e + residual)
__device__ float g_stats[8 * 128];      // sum/sq pairs: [0]=s1e,[256]=s1h,[512]=s2e,[768]=s2h
__device__ float g_bnp[8 * 128];        // mean/istd pairs, same offsets

// ---------------- zero accumulators ----------------
__global__ void k_zero() {
    int idx = blockIdx.x * blockDim.x + threadIdx.x;
    int stride = gridDim.x * blockDim.x;
    const int nwv = NN * D, nz = NN * 8, nst = 8 * 128;
    for (int i = idx; i < nwv; i += stride) g_wV[i] = 0.f;
    for (int i = idx; i < nz; i += stride) g_z[i] = 0.f;
    for (int i = idx; i < nst; i += stride) g_stats[i] = 0.f;
}

// ---------------- Q/K/V GEMMs: 128-row tiles ----------------
__global__ __launch_bounds__(256, 1) void k_qkv(const float* __restrict__ h,
                                                const float* __restrict__ Wq,
                                                const float* __restrict__ Wk,
                                                const float* __restrict__ Wv) {
    extern __shared__ float sm[];
    float* sA = sm;              // 128 x 132
    float* sB = sm + 128 * 132;  // 128 x 128
    const int tid = threadIdx.x, tx = tid & 15, ty = tid >> 4;
    const int row0 = blockIdx.x * 128;

    for (int i = tid; i < 128 * 32; i += 256) {
        int r = i >> 5, c4 = (i & 31) << 2;
        float4 v = make_float4(0.f, 0.f, 0.f, 0.f);
        if (row0 + r < NN) v = *(const float4*)(h + (row0 + r) * D + c4);
        *(float4*)(sA + r * 132 + c4) = v;
    }

    for (int wsel = 0; wsel < 3; wsel++) {
        const float* W = (wsel == 0) ? Wq : (wsel == 1) ? Wk : Wv;
        float* outp = (wsel == 0) ? g_Qh : (wsel == 1) ? g_Kh : g_Vh;
        __syncthreads();
        for (int i = tid; i < 128 * 32; i += 256) {
            int r = i >> 5, c4 = (i & 31) << 2;
            *(float4*)(sB + r * 128 + c4) = *(const float4*)(W + r * 128 + c4);
        }
        __syncthreads();

        float acc[8][8];
#pragma unroll
        for (int i = 0; i < 8; i++)
#pragma unroll
            for (int j = 0; j < 8; j++) acc[i][j] = 0.f;

#pragma unroll 1
        for (int k = 0; k < 128; k += 4) {
            float4 a[8];
#pragma unroll
            for (int i = 0; i < 8; i++) a[i] = *(const float4*)(sA + (ty * 8 + i) * 132 + k);
#pragma unroll
            for (int kk = 0; kk < 4; kk++) {
                float4 b0 = *(const float4*)(sB + (k + kk) * 128 + tx * 8);
                float4 b1 = *(const float4*)(sB + (k + kk) * 128 + tx * 8 + 4);
#pragma unroll
                for (int i = 0; i < 8; i++) {
                    float av = (kk == 0) ? a[i].x : (kk == 1) ? a[i].y : (kk == 2) ? a[i].z : a[i].w;
                    acc[i][0] += av * b0.x; acc[i][1] += av * b0.y;
                    acc[i][2] += av * b0.z; acc[i][3] += av * b0.w;
                    acc[i][4] += av * b1.x; acc[i][5] += av * b1.y;
                    acc[i][6] += av * b1.z; acc[i][7] += av * b1.w;
                }
            }
        }
#pragma unroll
        for (int i = 0; i < 8; i++) {
            int gr = row0 + ty * 8 + i;
            if (gr < NN) {
                *(float4*)(outp + gr * 128 + tx * 8) =
                    make_float4(acc[i][0], acc[i][1], acc[i][2], acc[i][3]);
                *(float4*)(outp + gr * 128 + tx * 8 + 4) =
                    make_float4(acc[i][4], acc[i][5], acc[i][6], acc[i][7]);
            }
        }
    }
}

// ---------------- fused edge kernel: pe, score, w, segment sums, Wo_e, residual, stats ----------------
__global__ __launch_bounds__(256, 1) void k_edge1(const float* __restrict__ e,
                                                  const int* __restrict__ src,
                                                  const int* __restrict__ dst,
                                                  const float* __restrict__ We,
                                                  const float* __restrict__ Wo_e,
                                                  const float* __restrict__ bo_e) {
    extern __shared__ float sm[];
    float* sE = sm;                    // 64 x 132 (e tile, kept for residual)
    float* sS = sE + 64 * 132;         // 64 x 132 (score)
    float* sW = sS + 64 * 132;         // 128 x 128
    float* swv = sW + 128 * 128;       // 64 x 8
    float* sCS = swv + 64 * 8;         // 128 col sums
    float* sCQ = sCS + 128;            // 128 col sq
    int* sSrc = (int*)(sCQ + 128);     // 64
    int* sDst = sSrc + 64;             // 64

    const int tid = threadIdx.x, tx = tid & 15, ty = tid >> 4;
    const int row0 = blockIdx.x * 64;

    for (int i = tid; i < 64 * 32; i += 256) {
        int r = i >> 5, c4 = (i & 31) << 2;
        *(float4*)(sE + r * 132 + c4) = *(const float4*)(e + (row0 + r) * D + c4);
    }
    for (int i = tid; i < 128 * 32; i += 256) {
        int r = i >> 5, c4 = (i & 31) << 2;
        *(float4*)(sW + r * 128 + c4) = *(const float4*)(We + r * 128 + c4);
    }
    if (tid < 64) { sSrc[tid] = src[row0 + tid]; sDst[tid] = dst[row0 + tid]; }
    if (tid < 128) { sCS[tid] = 0.f; sCQ[tid] = 0.f; }
    __syncthreads();

    // GEMM1: P = sE @ We (4 rows x 8 cols per thread)
    float acc[4][8];
#pragma unroll
    for (int i = 0; i < 4; i++)
#pragma unroll
        for (int j = 0; j < 8; j++) acc[i][j] = 0.f;

#pragma unroll 1
    for (int k = 0; k < 128; k += 4) {
        float4 a[4];
#pragma unroll
        for (int i = 0; i < 4; i++) a[i] = *(const float4*)(sE + (ty * 4 + i) * 132 + k);
#pragma unroll
        for (int kk = 0; kk < 4; kk++) {
            float4 b0 = *(const float4*)(sW + (k + kk) * 128 + tx * 8);
            float4 b1 = *(const float4*)(sW + (k + kk) * 128 + tx * 8 + 4);
#pragma unroll
            for (int i = 0; i < 4; i++) {
                float av = (kk == 0) ? a[i].x : (kk == 1) ? a[i].y : (kk == 2) ? a[i].z : a[i].w;
                acc[i][0] += av * b0.x; acc[i][1] += av * b0.y;
                acc[i][2] += av * b0.z; acc[i][3] += av * b0.w;
                acc[i][4] += av * b1.x; acc[i][5] += av * b1.y;
                acc[i][6] += av * b1.z; acc[i][7] += av * b1.w;
            }
        }
    }

    // score = P * Kh[src]*Qh[dst] / 4
#pragma unroll
    for (int i = 0; i < 4; i++) {
        int r = ty * 4 + i;
        int s = sSrc[r], d = sDst[r];
        float4 k0 = *(const float4*)(g_Kh + s * 128 + tx * 8);
        float4 k1 = *(const float4*)(g_Kh + s * 128 + tx * 8 + 4);
        float4 q0 = *(const float4*)(g_Qh + d * 128 + tx * 8);
        float4 q1 = *(const float4*)(g_Qh + d * 128 + tx * 8 + 4);
        float* sp = sS + r * 132 + tx * 8;
        sp[0] = acc[i][0] * k0.x * q0.x * 0.25f;
        sp[1] = acc[i][1] * k0.y * q0.y * 0.25f;
        sp[2] = acc[i][2] * k0.z * q0.z * 0.25f;
        sp[3] = acc[i][3] * k0.w * q0.w * 0.25f;
        sp[4] = acc[i][4] * k1.x * q1.x * 0.25f;
        sp[5] = acc[i][5] * k1.y * q1.y * 0.25f;
        sp[6] = acc[i][6] * k1.z * q1.z * 0.25f;
        sp[7] = acc[i][7] * k1.w * q1.w * 0.25f;
    }
    __syncthreads();

    // per-head weights w = exp(clip(sum_dh score)), z segment-sum
    for (int idx = tid; idx < 64 * 8; idx += 256) {
        int r = idx >> 3, hd = idx & 7;
        float ssum = 0.f;
#pragma unroll
        for (int t = 0; t < 16; t++) ssum += sS[r * 132 + hd * 16 + t];
        ssum = fminf(fmaxf(ssum, -5.f), 5.f);
        float wv = __expf(ssum);
        swv[idx] = wv;
        atomicAdd(&g_z[sDst[r] * 8 + hd], wv);
    }
    // reload weights with Wo_e while w finishes
    for (int i = tid; i < 128 * 32; i += 256) {
        int r = i >> 5, c4 = (i & 31) << 2;
        *(float4*)(sW + r * 128 + c4) = *(const float4*)(Wo_e + r * 128 + c4);
    }
    __syncthreads();

    // wV segment-sum (coalesced within each edge row)
    for (int idx = tid; idx < 64 * 128; idx += 256) {
        int r = idx >> 7, c = idx & 127;
        float v = g_Vh[sSrc[r] * 128 + c] * swv[r * 8 + (c >> 4)];
        atomicAdd(&g_wV[sDst[r] * 128 + c], v);
    }

    // GEMM2: ee = score @ Wo_e + bo_e + e
    float acc2[4][8];
#pragma unroll
    for (int i = 0; i < 4; i++)
#pragma unroll
        for (int j = 0; j < 8; j++) acc2[i][j] = 0.f;

#pragma unroll 1
    for (int k = 0; k < 128; k += 4) {
        float4 a[4];
#pragma unroll
        for (int i = 0; i < 4; i++) a[i] = *(const float4*)(sS + (ty * 4 + i) * 132 + k);
#pragma unroll
        for (int kk = 0; kk < 4; kk++) {
            float4 b0 = *(const float4*)(sW + (k + kk) * 128 + tx * 8);
            float4 b1 = *(const float4*)(sW + (k + kk) * 128 + tx * 8 + 4);
#pragma unroll
            for (int i = 0; i < 4; i++) {
                float av = (kk == 0) ? a[i].x : (kk == 1) ? a[i].y : (kk == 2) ? a[i].z : a[i].w;
                acc2[i][0] += av * b0.x; acc2[i][1] += av * b0.y;
                acc2[i][2] += av * b0.z; acc2[i][3] += av * b0.w;
                acc2[i][4] += av * b1.x; acc2[i][5] += av * b1.y;
                acc2[i][6] += av * b1.z; acc2[i][7] += av * b1.w;
            }
        }
    }

    float4 bb0 = *(const float4*)(bo_e + tx * 8);
    float4 bb1 = *(const float4*)(bo_e + tx * 8 + 4);
    float csum[8] = {0, 0, 0, 0, 0, 0, 0, 0};
    float csq[8] = {0, 0, 0, 0, 0, 0, 0, 0};
#pragma unroll
    for (int i = 0; i < 4; i++) {
        int r = ty * 4 + i;
        float o[8];
        o[0] = acc2[i][0] + bb0.x + sE[r * 132 + tx * 8 + 0];
        o[1] = acc2[i][1] + bb0.y + sE[r * 132 + tx * 8 + 1];
        o[2] = acc2[i][2] + bb0.z + sE[r * 132 + tx * 8 + 2];
        o[3] = acc2[i][3] + bb0.w + sE[r * 132 + tx * 8 + 3];
        o[4] = acc2[i][4] + bb1.x + sE[r * 132 + tx * 8 + 4];
        o[5] = acc2[i][5] + bb1.y + sE[r * 132 + tx * 8 + 5];
        o[6] = acc2[i][6] + bb1.z + sE[r * 132 + tx * 8 + 6];
        o[7] = acc2[i][7] + bb1.w + sE[r * 132 + tx * 8 + 7];
        *(float4*)(g_ee + (row0 + r) * 128 + tx * 8) = make_float4(o[0], o[1], o[2], o[3]);
        *(float4*)(g_ee + (row0 + r) * 128 + tx * 8 + 4) = make_float4(o[4], o[5], o[6], o[7]);
#pragma unroll
        for (int j = 0; j < 8; j++) { csum[j] += o[j]; csq[j] += o[j] * o[j]; }
    }
#pragma unroll
    for (int j = 0; j < 8; j++) {
        atomicAdd(&sCS[tx * 8 + j], csum[j]);
        atomicAdd(&sCQ[tx * 8 + j], csq[j]);
    }
    __syncthreads();
    if (tid < 128) {
        atomicAdd(&g_stats[0 * 128 + tid], sCS[tid]);
        atomicAdd(&g_stats[1 * 128 + tid], sCQ[tid]);
    }
}

// ---------------- node attention output: h_attn @ Wo_h + bo_h + h, stats ----------------
__global__ __launch_bounds__(256, 1) void k_nattn(const float* __restrict__ h,
                                                  const float* __restrict__ Wo_h,
                                                  const float* __restrict__ bo_h) {
    extern __shared__ float sm[];
    float* sA = sm;                   // 128 x 132
    float* sB = sm + 128 * 132;       // 128 x 128
    float* sCS = sB + 128 * 128;      // 128
    float* sCQ = sCS + 128;           // 128
    const int tid = threadIdx.x, tx = tid & 15, ty = tid >> 4;
    const int row0 = blockIdx.x * 128;

    for (int i = tid; i < 128 * 128; i += 256) {
        int r = i >> 7, c = i & 127;
        int gr = row0 + r;
        float v = 0.f;
        if (gr < NN) {
            float zz = g_z[gr * 8 + (c >> 4)];
            v = g_wV[gr * 128 + c] / (zz + 1e-6f);
        }
        sA[r * 132 + c] = v;
    }
    for (int i = tid; i < 128 * 32; i += 256) {
        int r = i >> 5, c4 = (i & 31) << 2;
        *(float4*)(sB + r * 128 + c4) = *(const float4*)(Wo_h + r * 128 + c4);
    }
    if (tid < 128) { sCS[tid] = 0.f; sCQ[tid] = 0.f; }
    __syncthreads();

    float acc[8][8];
#pragma unroll
    for (int i = 0; i < 8; i++)
#pragma unroll
        for (int j = 0; j < 8; j++) acc[i][j] = 0.f;

#pragma unroll 1
    for (int k = 0; k < 128; k += 4) {
        float4 a[8];
#pragma unroll
        for (int i = 0; i < 8; i++) a[i] = *(const float4*)(sA + (ty * 8 + i) * 132 + k);
#pragma unroll
        for (int kk = 0; kk < 4; kk++) {
            float4 b0 = *(const float4*)(sB + (k + kk) * 128 + tx * 8);
            float4 b1 = *(const float4*)(sB + (k + kk) * 128 + tx * 8 + 4);
#pragma unroll
            for (int i = 0; i < 8; i++) {
                float av = (kk == 0) ? a[i].x : (kk == 1) ? a[i].y : (kk == 2) ? a[i].z : a[i].w;
                acc[i][0] += av * b0.x; acc[i][1] += av * b0.y;
                acc[i][2] += av * b0.z; acc[i][3] += av * b0.w;
                acc[i][4] += av * b1.x; acc[i][5] += av * b1.y;
                acc[i][6] += av * b1.z; acc[i][7] += av * b1.w;
            }
        }
    }

    float4 bb0 = *(const float4*)(bo_h + tx * 8);
    float4 bb1 = *(const float4*)(bo_h + tx * 8 + 4);
    float csum[8] = {0, 0, 0, 0, 0, 0, 0, 0};
    float csq[8] = {0, 0, 0, 0, 0, 0, 0, 0};
#pragma unroll
    for (int i = 0; i < 8; i++) {
        int gr = row0 + ty * 8 + i;
        if (gr < NN) {
            float4 r0 = *(const float4*)(h + gr * 128 + tx * 8);
            float4 r1 = *(const float4*)(h + gr * 128 + tx * 8 + 4);
            float o[8];
            o[0] = acc[i][0] + bb0.x + r0.x; o[1] = acc[i][1] + bb0.y + r0.y;
            o[2] = acc[i][2] + bb0.z + r0.z; o[3] = acc[i][3] + bb0.w + r0.w;
            o[4] = acc[i][4] + bb1.x + r1.x; o[5] = acc[i][5] + bb1.y + r1.y;
            o[6] = acc[i][6] + bb1.z + r1.z; o[7] = acc[i][7] + bb1.w + r1.w;
            *(float4*)(g_hh + gr * 128 + tx * 8) = make_float4(o[0], o[1], o[2], o[3]);
            *(float4*)(g_hh + gr * 128 + tx * 8 + 4) = make_float4(o[4], o[5], o[6], o[7]);
#pragma unroll
            for (int j = 0; j < 8; j++) { csum[j] += o[j]; csq[j] += o[j] * o[j]; }
        }
    }
#pragma unroll
    for (int j = 0; j < 8; j++) {
        atomicAdd(&sCS[tx * 8 + j], csum[j]);
        atomicAdd(&sCQ[tx * 8 + j], csq[j]);
    }
    __syncthreads();
    if (tid < 128) {
        atomicAdd(&g_stats[2 * 128 + tid], sCS[tid]);
        atomicAdd(&g_stats[3 * 128 + tid], sCQ[tid]);
    }
}

// ---------------- finalize BN stats ----------------
__global__ void k_finalize(int statOff, float cnt, int bnOff) {
    int c = threadIdx.x;  // 128
    float m = g_stats[statOff + c] / cnt;
    float var = g_stats[statOff + 128 + c] / cnt - m * m;
    g_bnp[bnOff + c] = m;
    g_bnp[bnOff + 128 + c] = rsqrtf(var + 1e-5f);
}

// ---------------- fused BN1 + FFN + residual + stats2 ----------------
__global__ __launch_bounds__(256, 1) void k_ffn(const float* __restrict__ xin, float* xout,
                                                int bnOff,
                                                const float* __restrict__ gam,
                                                const float* __restrict__ bet,
                                                const float* __restrict__ W1,
                                                const float* __restrict__ b1,
                                                const float* __restrict__ W2,
                                                const float* __restrict__ b2,
                                                int statOff, int nrows) {
    extern __shared__ float sm[];
    float* sX = sm;                      // 128 x 132  (post-BN input, residual)
    float* sW1 = sX + 128 * 132;         // 128 x 64
    float* sY = sW1 + 128 * 64;          // 128 x 68
    float* sW2 = sY + 128 * 68;          // 64 x 128
    float* sCS = sW2 + 64 * 128;         // 128
    float* sCQ = sCS + 128;              // 128
    const int tid = threadIdx.x, tx = tid & 15, ty = tid >> 4;
    const int row0 = blockIdx.x * 128;
    const float* mean = g_bnp + bnOff;
    const float* istd = g_bnp + bnOff + 128;

    for (int i = tid; i < 128 * 128; i += 256) {
        int r = i >> 7, c = i & 127;
        int gr = row0 + r;
        float v = 0.f;
        if (gr < nrows) v = (xin[gr * 128 + c] - mean[c]) * istd[c] * gam[c] + bet[c];
        sX[r * 132 + c] = v;
    }
    if (tid < 128) { sCS[tid] = 0.f; sCQ[tid] = 0.f; }

    float accO[8][8];
#pragma unroll
    for (int i = 0; i < 8; i++)
#pragma unroll
        for (int j = 0; j < 8; j++) accO[i][j] = 0.f;

    for (int ch = 0; ch < 4; ch++) {
        __syncthreads();
        for (int i = tid; i < 128 * 16; i += 256) {
            int k = i >> 4, c4 = (i & 15) << 2;
            *(float4*)(sW1 + k * 64 + c4) = *(const float4*)(W1 + k * 256 + ch * 64 + c4);
        }
        for (int i = tid; i < 64 * 32; i += 256) {
            int k = i >> 5, c4 = (i & 31) << 2;
            *(float4*)(sW2 + k * 128 + c4) = *(const float4*)(W2 + (ch * 64 + k) * 128 + c4);
        }
        __syncthreads();

        // GEMM1: y = relu(sX @ W1chunk + b1chunk)   (8 rows x 4 cols / thread)
        float acc1[8][4];
#pragma unroll
        for (int i = 0; i < 8; i++)
#pragma unroll
            for (int j = 0; j < 4; j++) acc1[i][j] = 0.f;

#pragma unroll 1
        for (int k = 0; k < 128; k += 4) {
            float4 a[8];
#pragma unroll
            for (int i = 0; i < 8; i++) a[i] = *(const float4*)(sX + (ty * 8 + i) * 132 + k);
#pragma unroll
            for (int kk = 0; kk < 4; kk++) {
                float4 b = *(const float4*)(sW1 + (k + kk) * 64 + tx * 4);
#pragma unroll
                for (int i = 0; i < 8; i++) {
                    float av = (kk == 0) ? a[i].x : (kk == 1) ? a[i].y : (kk == 2) ? a[i].z : a[i].w;
                    acc1[i][0] += av * b.x; acc1[i][1] += av * b.y;
                    acc1[i][2] += av * b.z; acc1[i][3] += av * b.w;
                }
            }
        }
        float4 bb1 = *(const float4*)(b1 + ch * 64 + tx * 4);
#pragma unroll
        for (int i = 0; i < 8; i++) {
            int r = ty * 8 + i;
            sY[r * 68 + tx * 4 + 0] = fmaxf(acc1[i][0] + bb1.x, 0.f);
            sY[r * 68 + tx * 4 + 1] = fmaxf(acc1[i][1] + bb1.y, 0.f);
            sY[r * 68 + tx * 4 + 2] = fmaxf(acc1[i][2] + bb1.z, 0.f);
            sY[r * 68 + tx * 4 + 3] = fmaxf(acc1[i][3] + bb1.w, 0.f);
        }
        __syncthreads();

        // GEMM2 accumulate: out += y @ W2chunk
#pragma unroll 1
        for (int k = 0; k < 64; k += 4) {
            float4 a[8];
#pragma unroll
            for (int i = 0; i < 8; i++) a[i] = *(const float4*)(sY + (ty * 8 + i) * 68 + k);
#pragma unroll
            for (int kk = 0; kk < 4; kk++) {
                float4 b0 = *(const float4*)(sW2 + (k + kk) * 128 + tx * 8);
                float4 b1v = *(const float4*)(sW2 + (k + kk) * 128 + tx * 8 + 4);
#pragma unroll
                for (int i = 0; i < 8; i++) {
                    float av = (kk == 0) ? a[i].x : (kk == 1) ? a[i].y : (kk == 2) ? a[i].z : a[i].w;
                    accO[i][0] += av * b0.x; accO[i][1] += av * b0.y;
                    accO[i][2] += av * b0.z; accO[i][3] += av * b0.w;
                    accO[i][4] += av * b1v.x; accO[i][5] += av * b1v.y;
                    accO[i][6] += av * b1v.z; accO[i][7] += av * b1v.w;
                }
            }
        }
    }

    float4 c0 = *(const float4*)(b2 + tx * 8);
    float4 c1 = *(const float4*)(b2 + tx * 8 + 4);
    float csum[8] = {0, 0, 0, 0, 0, 0, 0, 0};
    float csq[8] = {0, 0, 0, 0, 0, 0, 0, 0};
#pragma unroll
    for (int i = 0; i < 8; i++) {
        int r = ty * 8 + i;
        int gr = row0 + r;
        if (gr < nrows) {
            float o[8];
            o[0] = accO[i][0] + c0.x + sX[r * 132 + tx * 8 + 0];
            o[1] = accO[i][1] + c0.y + sX[r * 132 + tx * 8 + 1];
            o[2] = accO[i][2] + c0.z + sX[r * 132 + tx * 8 + 2];
            o[3] = accO[i][3] + c0.w + sX[r * 132 + tx * 8 + 3];
            o[4] = accO[i][4] + c1.x + sX[r * 132 + tx * 8 + 4];
            o[5] = accO[i][5] + c1.y + sX[r * 132 + tx * 8 + 5];
            o[6] = accO[i][6] + c1.z + sX[r * 132 + tx * 8 + 6];
            o[7] = accO[i][7] + c1.w + sX[r * 132 + tx * 8 + 7];
            *(float4*)(xout + (size_t)gr * 128 + tx * 8) = make_float4(o[0], o[1], o[2], o[3]);
            *(float4*)(xout + (size_t)gr * 128 + tx * 8 + 4) = make_float4(o[4], o[5], o[6], o[7]);
#pragma unroll
            for (int j = 0; j < 8; j++) { csum[j] += o[j]; csq[j] += o[j] * o[j]; }
        }
    }
#pragma unroll
    for (int j = 0; j < 8; j++) {
        atomicAdd(&sCS[tx * 8 + j], csum[j]);
        atomicAdd(&sCQ[tx * 8 + j], csq[j]);
    }
    __syncthreads();
    if (tid < 128) {
        atomicAdd(&g_stats[statOff + tid], sCS[tid]);
        atomicAdd(&g_stats[statOff + 128 + tid], sCQ[tid]);
    }
}

// ---------------- final BN (elementwise, may be in-place) ----------------
__global__ void k_bnout(const float* x, int bnOff, const float* gam, const float* bet,
                        float* o, int nrows) {
    const float* mean = g_bnp + bnOff;
    const float* istd = g_bnp + bnOff + 128;
    int idx = blockIdx.x * blockDim.x + threadIdx.x;
    int stride = gridDim.x * blockDim.x;
    int total = nrows * 32;  // float4 units
    for (int i = idx; i < total; i += stride) {
        int c = (i & 31) << 2;
        float4 v = *(const float4*)(x + (size_t)i * 4);
        float4 r;
        r.x = (v.x - mean[c + 0]) * istd[c + 0] * gam[c + 0] + bet[c + 0];
        r.y = (v.y - mean[c + 1]) * istd[c + 1] * gam[c + 1] + bet[c + 1];
        r.z = (v.z - mean[c + 2]) * istd[c + 2] * gam[c + 2] + bet[c + 2];
        r.w = (v.w - mean[c + 3]) * istd[c + 3] * gam[c + 3] + bet[c + 3];
        *(float4*)(o + (size_t)i * 4) = r;
    }
}

// ---------------- launch ----------------
extern "C" void kernel_launch(void* const* d_in, const int* in_sizes, int n_in,
                              void* d_out, int out_size) {
    const float* h = (const float*)d_in[0];
    const float* e = (const float*)d_in[1];
    const int* src = (const int*)d_in[2];
    const int* dst = (const int*)d_in[3];
    const float* Wq = (const float*)d_in[4];
    const float* Wk = (const float*)d_in[5];
    const float* Wv = (const float*)d_in[6];
    const float* We = (const float*)d_in[7];
    const float* Wo_h = (const float*)d_in[8];
    const float* bo_h = (const float*)d_in[9];
    const float* Wo_e = (const float*)d_in[10];
    const float* bo_e = (const float*)d_in[11];
    const float* g1h = (const float*)d_in[12];
    const float* b1h = (const float*)d_in[13];
    const float* g1e = (const float*)d_in[14];
    const float* b1e = (const float*)d_in[15];
    const float* Wf1h = (const float*)d_in[16];
    const float* bf1h = (const float*)d_in[17];
    const float* Wf2h = (const float*)d_in[18];
    const float* bf2h = (const float*)d_in[19];
    const float* Wf1e = (const float*)d_in[20];
    const float* bf1e = (const float*)d_in[21];
    const float* Wf2e = (const float*)d_in[22];
    const float* bf2e = (const float*)d_in[23];
    const float* g2h = (const float*)d_in[24];
    const float* b2h = (const float*)d_in[25];
    const float* g2e = (const float*)d_in[26];
    const float* b2e = (const float*)d_in[27];
    float* out = (float*)d_out;
    float* out_e = out + (size_t)NN * D;

    float *p_hh, *p_h2, *p_ee;
    cudaGetSymbolAddress((void**)&p_hh, g_hh);
    cudaGetSymbolAddress((void**)&p_h2, g_h2);
    cudaGetSymbolAddress((void**)&p_ee, g_ee);

    const int smA = (128 * 132 + 128 * 128 + 256) * 4;
    const int sm1 = (64 * 132 * 2 + 128 * 128 + 64 * 8 + 256 + 128) * 4;
    const int smF = (128 * 132 + 128 * 64 + 128 * 68 + 64 * 128 + 256) * 4;
    cudaFuncSetAttribute(k_qkv, cudaFuncAttributeMaxDynamicSharedMemorySize, smA);
    cudaFuncSetAttribute(k_nattn, cudaFuncAttributeMaxDynamicSharedMemorySize, smA);
    cudaFuncSetAttribute(k_edge1, cudaFuncAttributeMaxDynamicSharedMemorySize, sm1);
    cudaFuncSetAttribute(k_ffn, cudaFuncAttributeMaxDynamicSharedMemorySize, smF);

    const int NBLK = (NN + 127) / 128;  // 391

    k_zero<<<2048, 256>>>();
    k_qkv<<<NBLK, 256, smA>>>(h, Wq, Wk, Wv);
    k_edge1<<<NE / 64, 256, sm1>>>(e, src, dst, We, Wo_e, bo_e);
    k_nattn<<<NBLK, 256, smA>>>(h, Wo_h, bo_h);
    k_finalize<<<1, 128>>>(0, (float)NE, 0);      // bn1e
    k_finalize<<<1, 128>>>(256, (float)NN, 256);  // bn1h
    k_ffn<<<NE / 128, 256, smF>>>(p_ee, out_e, 0, g1e, b1e, Wf1e, bf1e, Wf2e, bf2e, 512, NE);
    k_ffn<<<NBLK, 256, smF>>>(p_hh, p_h2, 256, g1h, b1h, Wf1h, bf1h, Wf2h, bf2h, 768, NN);
    k_finalize<<<1, 128>>>(512, (float)NE, 512);  // bn2e
    k_finalize<<<1, 128>>>(768, (float)NN, 768);  // bn2h
    k_bnout<<<2960, 256>>>(p_h2, 768, g2h, b2h, out, NN);
    k_bnout<<<2960, 256>>>(out_e, 512, g2e, b2e, out_e, NE);
}

// round 5
// speedup vs baseline: 1.4642x; 1.4642x over previous
#include <cuda_runtime.h>
#include <math.h>
#include <stdint.h>

#define NN 50000
#define NE 640000
#define D 128

// ---------------- scratch (device globals; no cudaMalloc allowed) ----------------
__device__ float g_Qh[NN * D];
__device__ float g_Kh[NN * D];
__device__ float g_Vh[NN * D];
__device__ float g_wV[NN * D];
__device__ float g_z[NN * 8];
__device__ float g_hh[NN * D];
__device__ float g_h2[NN * D];
__device__ float g_ee[NE * D];
__device__ float g_stats[8 * 128];
__device__ float g_bnp[8 * 128];

// ---------------- tf32 mma helpers ----------------
__device__ __forceinline__ uint32_t f2tf(float x) {
    uint32_t r;
    asm("cvt.rna.tf32.f32 %0, %1;" : "=r"(r) : "f"(x));
    return r;
}
__device__ __forceinline__ float f2tf_f(float x) { return __uint_as_float(f2tf(x)); }

__device__ __forceinline__ void mma8(float c[4], const uint32_t a[4], uint32_t b0, uint32_t b1) {
    asm volatile(
        "mma.sync.aligned.m16n8k8.row.col.f32.tf32.tf32.f32 "
        "{%0,%1,%2,%3}, {%4,%5,%6,%7}, {%8,%9}, {%0,%1,%2,%3};"
        : "+f"(c[0]), "+f"(c[1]), "+f"(c[2]), "+f"(c[3])
        : "r"(a[0]), "r"(a[1]), "r"(a[2]), "r"(a[3]), "r"(b0), "r"(b1));
}

// ---------------- zero accumulators ----------------
__global__ void k_zero() {
    int idx = blockIdx.x * blockDim.x + threadIdx.x;
    int stride = gridDim.x * blockDim.x;
    const int nwv = NN * D, nz = NN * 8, nst = 8 * 128;
    for (int i = idx; i < nwv; i += stride) g_wV[i] = 0.f;
    for (int i = idx; i < nz; i += stride) g_z[i] = 0.f;
    for (int i = idx; i < nst; i += stride) g_stats[i] = 0.f;
}

// ---------------- Q/K/V GEMMs (FFMA; small share of total flops) ----------------
__global__ __launch_bounds__(256, 1) void k_qkv(const float* __restrict__ h,
                                                const float* __restrict__ Wq,
                                                const float* __restrict__ Wk,
                                                const float* __restrict__ Wv) {
    extern __shared__ float sm[];
    float* sA = sm;              // 128 x 132
    float* sB = sm + 128 * 132;  // 128 x 128
    const int tid = threadIdx.x, tx = tid & 15, ty = tid >> 4;
    const int row0 = blockIdx.x * 128;

    for (int i = tid; i < 128 * 32; i += 256) {
        int r = i >> 5, c4 = (i & 31) << 2;
        float4 v = make_float4(0.f, 0.f, 0.f, 0.f);
        if (row0 + r < NN) v = *(const float4*)(h + (row0 + r) * D + c4);
        *(float4*)(sA + r * 132 + c4) = v;
    }

    for (int wsel = 0; wsel < 3; wsel++) {
        const float* W = (wsel == 0) ? Wq : (wsel == 1) ? Wk : Wv;
        float* outp = (wsel == 0) ? g_Qh : (wsel == 1) ? g_Kh : g_Vh;
        __syncthreads();
        for (int i = tid; i < 128 * 32; i += 256) {
            int r = i >> 5, c4 = (i & 31) << 2;
            *(float4*)(sB + r * 128 + c4) = *(const float4*)(W + r * 128 + c4);
        }
        __syncthreads();

        float acc[8][8];
#pragma unroll
        for (int i = 0; i < 8; i++)
#pragma unroll
            for (int j = 0; j < 8; j++) acc[i][j] = 0.f;

#pragma unroll 1
        for (int k = 0; k < 128; k += 4) {
            float4 a[8];
#pragma unroll
            for (int i = 0; i < 8; i++) a[i] = *(const float4*)(sA + (ty * 8 + i) * 132 + k);
#pragma unroll
            for (int kk = 0; kk < 4; kk++) {
                float4 b0 = *(const float4*)(sB + (k + kk) * 128 + tx * 8);
                float4 b1 = *(const float4*)(sB + (k + kk) * 128 + tx * 8 + 4);
#pragma unroll
                for (int i = 0; i < 8; i++) {
                    float av = (kk == 0) ? a[i].x : (kk == 1) ? a[i].y : (kk == 2) ? a[i].z : a[i].w;
                    acc[i][0] += av * b0.x; acc[i][1] += av * b0.y;
                    acc[i][2] += av * b0.z; acc[i][3] += av * b0.w;
                    acc[i][4] += av * b1.x; acc[i][5] += av * b1.y;
                    acc[i][6] += av * b1.z; acc[i][7] += av * b1.w;
                }
            }
        }
#pragma unroll
        for (int i = 0; i < 8; i++) {
            int gr = row0 + ty * 8 + i;
            if (gr < NN) {
                *(float4*)(outp + gr * 128 + tx * 8) =
                    make_float4(acc[i][0], acc[i][1], acc[i][2], acc[i][3]);
                *(float4*)(outp + gr * 128 + tx * 8 + 4) =
                    make_float4(acc[i][4], acc[i][5], acc[i][6], acc[i][7]);
            }
        }
    }
}

// ---------------- fused edge kernel (tensor-core tf32 GEMMs) ----------------
__global__ __launch_bounds__(256, 1) void k_edge1(const float* __restrict__ e,
                                                  const int* __restrict__ src,
                                                  const int* __restrict__ dst,
                                                  const float* __restrict__ We,
                                                  const float* __restrict__ Wo_e,
                                                  const float* __restrict__ bo_e) {
    extern __shared__ float sm[];
    float* sE = sm;                    // 64 x 132  (e tile, fp32, residual)
    float* sS = sE + 64 * 132;         // 64 x 132  (P then score, fp32)
    float* sO = sS + 64 * 132;         // 64 x 132  (GEMM2 out staging)
    float* sW = sO + 64 * 132;         // 128 x 136 (tf32 weights)
    float* swv = sW + 128 * 136;       // 64 x 8
    float* sCS = swv + 512;            // 128
    float* sCQ = sCS + 128;            // 128
    int* sSrc = (int*)(sCQ + 128);     // 64
    int* sDst = sSrc + 64;             // 64

    const int tid = threadIdx.x;
    const int lane = tid & 31, wid = tid >> 5;
    const int g = lane >> 2, q = lane & 3;
    const int wm = wid >> 1, wn = wid & 1;   // 4 m-tiles of 16 rows, 2 n-halves of 64 cols
    const int mr = wm * 16, nc0 = wn * 64;
    const int row0 = blockIdx.x * 64;

    for (int i = tid; i < 64 * 32; i += 256) {
        int r = i >> 5, c4 = (i & 31) << 2;
        *(float4*)(sE + r * 132 + c4) = *(const float4*)(e + (row0 + r) * D + c4);
    }
    for (int i = tid; i < 128 * 32; i += 256) {
        int r = i >> 5, c4 = (i & 31) << 2;
        float4 w = *(const float4*)(We + r * 128 + c4);
        sW[r * 136 + c4 + 0] = f2tf_f(w.x);
        sW[r * 136 + c4 + 1] = f2tf_f(w.y);
        sW[r * 136 + c4 + 2] = f2tf_f(w.z);
        sW[r * 136 + c4 + 3] = f2tf_f(w.w);
    }
    if (tid < 64) { sSrc[tid] = src[row0 + tid]; sDst[tid] = dst[row0 + tid]; }
    if (tid < 128) { sCS[tid] = 0.f; sCQ[tid] = 0.f; }
    __syncthreads();

    // GEMM1: P = e @ We   (warp: 16 rows x 64 cols = 1x8 m16n8k8 tiles)
    {
        float c1[8][4];
#pragma unroll
        for (int n = 0; n < 8; n++)
#pragma unroll
            for (int j = 0; j < 4; j++) c1[n][j] = 0.f;

#pragma unroll 2
        for (int k0 = 0; k0 < 128; k0 += 8) {
            uint32_t a[4];
            a[0] = f2tf(sE[(mr + g) * 132 + k0 + q]);
            a[1] = f2tf(sE[(mr + g + 8) * 132 + k0 + q]);
            a[2] = f2tf(sE[(mr + g) * 132 + k0 + q + 4]);
            a[3] = f2tf(sE[(mr + g + 8) * 132 + k0 + q + 4]);
#pragma unroll
            for (int n = 0; n < 8; n++) {
                uint32_t b0 = __float_as_uint(sW[(k0 + q) * 136 + nc0 + n * 8 + g]);
                uint32_t b1 = __float_as_uint(sW[(k0 + q + 4) * 136 + nc0 + n * 8 + g]);
                mma8(c1[n], a, b0, b1);
            }
        }
#pragma unroll
        for (int n = 0; n < 8; n++) {
            int cc = nc0 + n * 8 + 2 * q;
            sS[(mr + g) * 132 + cc] = c1[n][0];
            sS[(mr + g) * 132 + cc + 1] = c1[n][1];
            sS[(mr + g + 8) * 132 + cc] = c1[n][2];
            sS[(mr + g + 8) * 132 + cc + 1] = c1[n][3];
        }
    }
    __syncthreads();

    // score = P * Kh[src] * Qh[dst] / 4  (in place, coalesced)
    for (int i = tid; i < 64 * 32; i += 256) {
        int r = i >> 5, c4 = (i & 31) << 2;
        int s = sSrc[r], d = sDst[r];
        float4 p = *(float4*)(sS + r * 132 + c4);
        float4 kv = *(const float4*)(g_Kh + s * 128 + c4);
        float4 qv = *(const float4*)(g_Qh + d * 128 + c4);
        p.x *= kv.x * qv.x * 0.25f;
        p.y *= kv.y * qv.y * 0.25f;
        p.z *= kv.z * qv.z * 0.25f;
        p.w *= kv.w * qv.w * 0.25f;
        *(float4*)(sS + r * 132 + c4) = p;
    }
    __syncthreads();

    // per-head weights + z segment-sum; refill sW with Wo_e (tf32)
    for (int idx = tid; idx < 64 * 8; idx += 256) {
        int r = idx >> 3, hd = idx & 7;
        float ssum = 0.f;
#pragma unroll
        for (int t = 0; t < 16; t++) ssum += sS[r * 132 + hd * 16 + t];
        ssum = fminf(fmaxf(ssum, -5.f), 5.f);
        float wv = __expf(ssum);
        swv[idx] = wv;
        atomicAdd(&g_z[sDst[r] * 8 + hd], wv);
    }
    for (int i = tid; i < 128 * 32; i += 256) {
        int r = i >> 5, c4 = (i & 31) << 2;
        float4 w = *(const float4*)(Wo_e + r * 128 + c4);
        sW[r * 136 + c4 + 0] = f2tf_f(w.x);
        sW[r * 136 + c4 + 1] = f2tf_f(w.y);
        sW[r * 136 + c4 + 2] = f2tf_f(w.z);
        sW[r * 136 + c4 + 3] = f2tf_f(w.w);
    }
    __syncthreads();

    // wV segment-sum
    for (int idx = tid; idx < 64 * 128; idx += 256) {
        int r = idx >> 7, c = idx & 127;
        float v = g_Vh[sSrc[r] * 128 + c] * swv[r * 8 + (c >> 4)];
        atomicAdd(&g_wV[sDst[r] * 128 + c], v);
    }

    // GEMM2: ee_pre = score @ Wo_e
    {
        float c2[8][4];
#pragma unroll
        for (int n = 0; n < 8; n++)
#pragma unroll
            for (int j = 0; j < 4; j++) c2[n][j] = 0.f;

#pragma unroll 2
        for (int k0 = 0; k0 < 128; k0 += 8) {
            uint32_t a[4];
            a[0] = f2tf(sS[(mr + g) * 132 + k0 + q]);
            a[1] = f2tf(sS[(mr + g + 8) * 132 + k0 + q]);
            a[2] = f2tf(sS[(mr + g) * 132 + k0 + q + 4]);
            a[3] = f2tf(sS[(mr + g + 8) * 132 + k0 + q + 4]);
#pragma unroll
            for (int n = 0; n < 8; n++) {
                uint32_t b0 = __float_as_uint(sW[(k0 + q) * 136 + nc0 + n * 8 + g]);
                uint32_t b1 = __float_as_uint(sW[(k0 + q + 4) * 136 + nc0 + n * 8 + g]);
                mma8(c2[n], a, b0, b1);
            }
        }
#pragma unroll
        for (int n = 0; n < 8; n++) {
            int cc = nc0 + n * 8 + 2 * q;
            sO[(mr + g) * 132 + cc] = c2[n][0];
            sO[(mr + g) * 132 + cc + 1] = c2[n][1];
            sO[(mr + g + 8) * 132 + cc] = c2[n][2];
            sO[(mr + g + 8) * 132 + cc + 1] = c2[n][3];
        }
    }
    __syncthreads();

    // epilogue: bias + residual + store + stats
    const int tx = tid & 15, ty = tid >> 4;
    float4 bb0 = *(const float4*)(bo_e + tx * 8);
    float4 bb1 = *(const float4*)(bo_e + tx * 8 + 4);
    float bias[8] = {bb0.x, bb0.y, bb0.z, bb0.w, bb1.x, bb1.y, bb1.z, bb1.w};
    float csum[8] = {0, 0, 0, 0, 0, 0, 0, 0};
    float csq[8] = {0, 0, 0, 0, 0, 0, 0, 0};
#pragma unroll
    for (int i = 0; i < 4; i++) {
        int r = ty * 4 + i;
        float o[8];
#pragma unroll
        for (int j = 0; j < 8; j++) {
            o[j] = sO[r * 132 + tx * 8 + j] + bias[j] + sE[r * 132 + tx * 8 + j];
            csum[j] += o[j];
            csq[j] += o[j] * o[j];
        }
        *(float4*)(g_ee + (row0 + r) * 128 + tx * 8) = make_float4(o[0], o[1], o[2], o[3]);
        *(float4*)(g_ee + (row0 + r) * 128 + tx * 8 + 4) = make_float4(o[4], o[5], o[6], o[7]);
    }
#pragma unroll
    for (int j = 0; j < 8; j++) {
        atomicAdd(&sCS[tx * 8 + j], csum[j]);
        atomicAdd(&sCQ[tx * 8 + j], csq[j]);
    }
    __syncthreads();
    if (tid < 128) {
        atomicAdd(&g_stats[0 * 128 + tid], sCS[tid]);
        atomicAdd(&g_stats[1 * 128 + tid], sCQ[tid]);
    }
}

// ---------------- node attention output (FFMA; small) ----------------
__global__ __launch_bounds__(256, 1) void k_nattn(const float* __restrict__ h,
                                                  const float* __restrict__ Wo_h,
                                                  const float* __restrict__ bo_h) {
    extern __shared__ float sm[];
    float* sA = sm;                   // 128 x 132
    float* sB = sm + 128 * 132;       // 128 x 128
    float* sCS = sB + 128 * 128;      // 128
    float* sCQ = sCS + 128;           // 128
    const int tid = threadIdx.x, tx = tid & 15, ty = tid >> 4;
    const int row0 = blockIdx.x * 128;

    for (int i = tid; i < 128 * 128; i += 256) {
        int r = i >> 7, c = i & 127;
        int gr = row0 + r;
        float v = 0.f;
        if (gr < NN) {
            float zz = g_z[gr * 8 + (c >> 4)];
            v = g_wV[gr * 128 + c] / (zz + 1e-6f);
        }
        sA[r * 132 + c] = v;
    }
    for (int i = tid; i < 128 * 32; i += 256) {
        int r = i >> 5, c4 = (i & 31) << 2;
        *(float4*)(sB + r * 128 + c4) = *(const float4*)(Wo_h + r * 128 + c4);
    }
    if (tid < 128) { sCS[tid] = 0.f; sCQ[tid] = 0.f; }
    __syncthreads();

    float acc[8][8];
#pragma unroll
    for (int i = 0; i < 8; i++)
#pragma unroll
        for (int j = 0; j < 8; j++) acc[i][j] = 0.f;

#pragma unroll 1
    for (int k = 0; k < 128; k += 4) {
        float4 a[8];
#pragma unroll
        for (int i = 0; i < 8; i++) a[i] = *(const float4*)(sA + (ty * 8 + i) * 132 + k);
#pragma unroll
        for (int kk = 0; kk < 4; kk++) {
            float4 b0 = *(const float4*)(sB + (k + kk) * 128 + tx * 8);
            float4 b1 = *(const float4*)(sB + (k + kk) * 128 + tx * 8 + 4);
#pragma unroll
            for (int i = 0; i < 8; i++) {
                float av = (kk == 0) ? a[i].x : (kk == 1) ? a[i].y : (kk == 2) ? a[i].z : a[i].w;
                acc[i][0] += av * b0.x; acc[i][1] += av * b0.y;
                acc[i][2] += av * b0.z; acc[i][3] += av * b0.w;
                acc[i][4] += av * b1.x; acc[i][5] += av * b1.y;
                acc[i][6] += av * b1.z; acc[i][7] += av * b1.w;
            }
        }
    }

    float4 bb0 = *(const float4*)(bo_h + tx * 8);
    float4 bb1 = *(const float4*)(bo_h + tx * 8 + 4);
    float csum[8] = {0, 0, 0, 0, 0, 0, 0, 0};
    float csq[8] = {0, 0, 0, 0, 0, 0, 0, 0};
#pragma unroll
    for (int i = 0; i < 8; i++) {
        int gr = row0 + ty * 8 + i;
        if (gr < NN) {
            float4 r0 = *(const float4*)(h + gr * 128 + tx * 8);
            float4 r1 = *(const float4*)(h + gr * 128 + tx * 8 + 4);
            float o[8];
            o[0] = acc[i][0] + bb0.x + r0.x; o[1] = acc[i][1] + bb0.y + r0.y;
            o[2] = acc[i][2] + bb0.z + r0.z; o[3] = acc[i][3] + bb0.w + r0.w;
            o[4] = acc[i][4] + bb1.x + r1.x; o[5] = acc[i][5] + bb1.y + r1.y;
            o[6] = acc[i][6] + bb1.z + r1.z; o[7] = acc[i][7] + bb1.w + r1.w;
            *(float4*)(g_hh + gr * 128 + tx * 8) = make_float4(o[0], o[1], o[2], o[3]);
            *(float4*)(g_hh + gr * 128 + tx * 8 + 4) = make_float4(o[4], o[5], o[6], o[7]);
#pragma unroll
            for (int j = 0; j < 8; j++) { csum[j] += o[j]; csq[j] += o[j] * o[j]; }
        }
    }
#pragma unroll
    for (int j = 0; j < 8; j++) {
        atomicAdd(&sCS[tx * 8 + j], csum[j]);
        atomicAdd(&sCQ[tx * 8 + j], csq[j]);
    }
    __syncthreads();
    if (tid < 128) {
        atomicAdd(&g_stats[2 * 128 + tid], sCS[tid]);
        atomicAdd(&g_stats[3 * 128 + tid], sCQ[tid]);
    }
}

// ---------------- finalize BN stats ----------------
__global__ void k_finalize(int statOff, float cnt, int bnOff) {
    int c = threadIdx.x;  // 128
    float m = g_stats[statOff + c] / cnt;
    float var = g_stats[statOff + 128 + c] / cnt - m * m;
    g_bnp[bnOff + c] = m;
    g_bnp[bnOff + 128 + c] = rsqrtf(var + 1e-5f);
}

// ---------------- fused BN1 + FFN + residual + stats2 (tensor-core tf32) ----------------
__global__ __launch_bounds__(256, 1) void k_ffn(const float* __restrict__ xin, float* xout,
                                                int bnOff,
                                                const float* __restrict__ gam,
                                                const float* __restrict__ bet,
                                                const float* __restrict__ Wa,
                                                const float* __restrict__ ba,
                                                const float* __restrict__ Wb,
                                                const float* __restrict__ bb2,
                                                int statOff, int nrows) {
    extern __shared__ float sm[];
    float* sX = sm;                      // 128 x 132 (post-BN input fp32, residual)
    float* sW1 = sX + 128 * 132;         // 128 x 72 (tf32 W1 chunk)
    float* sY = sW1 + 128 * 72;          // 128 x 68 (tf32 relu output)
    float* sW2 = sY + 128 * 68;          // 64 x 136 (tf32 W2 chunk)
    float* sCS = sW2 + 64 * 136;         // 128
    float* sCQ = sCS + 128;              // 128
    float* sO = sW1;                     // overlay: 128 x 132 output staging (after loops)

    const int tid = threadIdx.x;
    const int lane = tid & 31, wid = tid >> 5;
    const int g = lane >> 2, q = lane & 3;
    const int wm = wid >> 1, wn = wid & 1;   // warp: rows wm*32 (2 m16 tiles)
    const int row0 = blockIdx.x * 128;
    const float* mean = g_bnp + bnOff;
    const float* istd = g_bnp + bnOff + 128;

    for (int i = tid; i < 128 * 128; i += 256) {
        int r = i >> 7, c = i & 127;
        int gr = row0 + r;
        float v = 0.f;
        if (gr < nrows) v = (xin[(size_t)gr * 128 + c] - mean[c]) * istd[c] * gam[c] + bet[c];
        sX[r * 132 + c] = v;
    }
    if (tid < 128) { sCS[tid] = 0.f; sCQ[tid] = 0.f; }

    float accO[2][8][4];   // rows wm*32 + m*16, cols wn*64 + n*8
#pragma unroll
    for (int m = 0; m < 2; m++)
#pragma unroll
        for (int n = 0; n < 8; n++)
#pragma unroll
            for (int j = 0; j < 4; j++) accO[m][n][j] = 0.f;

    for (int ch = 0; ch < 4; ch++) {
        __syncthreads();
        for (int i = tid; i < 128 * 16; i += 256) {
            int k = i >> 4, c4 = (i & 15) << 2;
            float4 w = *(const float4*)(Wa + k * 256 + ch * 64 + c4);
            sW1[k * 72 + c4 + 0] = f2tf_f(w.x);
            sW1[k * 72 + c4 + 1] = f2tf_f(w.y);
            sW1[k * 72 + c4 + 2] = f2tf_f(w.z);
            sW1[k * 72 + c4 + 3] = f2tf_f(w.w);
        }
        for (int i = tid; i < 64 * 32; i += 256) {
            int k = i >> 5, c4 = (i & 31) << 2;
            float4 w = *(const float4*)(Wb + (ch * 64 + k) * 128 + c4);
            sW2[k * 136 + c4 + 0] = f2tf_f(w.x);
            sW2[k * 136 + c4 + 1] = f2tf_f(w.y);
            sW2[k * 136 + c4 + 2] = f2tf_f(w.z);
            sW2[k * 136 + c4 + 3] = f2tf_f(w.w);
        }
        __syncthreads();

        // GEMM1: y = relu(sX @ W1chunk + b1chunk)  (warp: 32 rows x 32 cols)
        float c1[2][4][4];
#pragma unroll
        for (int m = 0; m < 2; m++)
#pragma unroll
            for (int n = 0; n < 4; n++)
#pragma unroll
                for (int j = 0; j < 4; j++) c1[m][n][j] = 0.f;

        const int nb = wn * 32;
#pragma unroll 2
        for (int k0 = 0; k0 < 128; k0 += 8) {
            uint32_t a[2][4];
#pragma unroll
            for (int m = 0; m < 2; m++) {
                int rr = wm * 32 + m * 16;
                a[m][0] = f2tf(sX[(rr + g) * 132 + k0 + q]);
                a[m][1] = f2tf(sX[(rr + g + 8) * 132 + k0 + q]);
                a[m][2] = f2tf(sX[(rr + g) * 132 + k0 + q + 4]);
                a[m][3] = f2tf(sX[(rr + g + 8) * 132 + k0 + q + 4]);
            }
#pragma unroll
            for (int n = 0; n < 4; n++) {
                uint32_t b0 = __float_as_uint(sW1[(k0 + q) * 72 + nb + n * 8 + g]);
                uint32_t b1 = __float_as_uint(sW1[(k0 + q + 4) * 72 + nb + n * 8 + g]);
                mma8(c1[0][n], a[0], b0, b1);
                mma8(c1[1][n], a[1], b0, b1);
            }
        }
        // bias + relu -> sY (pre-converted tf32)
#pragma unroll
        for (int m = 0; m < 2; m++)
#pragma unroll
            for (int n = 0; n < 4; n++) {
                int cc = nb + n * 8 + 2 * q;
                float bv0 = ba[ch * 64 + cc], bv1 = ba[ch * 64 + cc + 1];
                int r0 = wm * 32 + m * 16 + g, r1 = r0 + 8;
                sY[r0 * 68 + cc] = f2tf_f(fmaxf(c1[m][n][0] + bv0, 0.f));
                sY[r0 * 68 + cc + 1] = f2tf_f(fmaxf(c1[m][n][1] + bv1, 0.f));
                sY[r1 * 68 + cc] = f2tf_f(fmaxf(c1[m][n][2] + bv0, 0.f));
                sY[r1 * 68 + cc + 1] = f2tf_f(fmaxf(c1[m][n][3] + bv1, 0.f));
            }
        __syncthreads();

        // GEMM2 accumulate: out += y @ W2chunk  (warp: 32 rows x 64 cols)
#pragma unroll 2
        for (int k0 = 0; k0 < 64; k0 += 8) {
            uint32_t a[2][4];
#pragma unroll
            for (int m = 0; m < 2; m++) {
                int rr = wm * 32 + m * 16;
                a[m][0] = __float_as_uint(sY[(rr + g) * 68 + k0 + q]);
                a[m][1] = __float_as_uint(sY[(rr + g + 8) * 68 + k0 + q]);
                a[m][2] = __float_as_uint(sY[(rr + g) * 68 + k0 + q + 4]);
                a[m][3] = __float_as_uint(sY[(rr + g + 8) * 68 + k0 + q + 4]);
            }
#pragma unroll
            for (int n = 0; n < 8; n++) {
                uint32_t b0 = __float_as_uint(sW2[(k0 + q) * 136 + wn * 64 + n * 8 + g]);
                uint32_t b1 = __float_as_uint(sW2[(k0 + q + 4) * 136 + wn * 64 + n * 8 + g]);
                mma8(accO[0][n], a[0], b0, b1);
                mma8(accO[1][n], a[1], b0, b1);
            }
        }
    }
    __syncthreads();   // all warps done reading sW1/sY before overlay stores

    // stage output frags to sO
#pragma unroll
    for (int m = 0; m < 2; m++)
#pragma unroll
        for (int n = 0; n < 8; n++) {
            int r0 = wm * 32 + m * 16 + g, r1 = r0 + 8;
            int cc = wn * 64 + n * 8 + 2 * q;
            sO[r0 * 132 + cc] = accO[m][n][0];
            sO[r0 * 132 + cc + 1] = accO[m][n][1];
            sO[r1 * 132 + cc] = accO[m][n][2];
            sO[r1 * 132 + cc + 1] = accO[m][n][3];
        }
    __syncthreads();

    // epilogue: bias + residual + store + stats
    const int tx = tid & 15, ty = tid >> 4;
    float4 c0 = *(const float4*)(bb2 + tx * 8);
    float4 c1v = *(const float4*)(bb2 + tx * 8 + 4);
    float bias[8] = {c0.x, c0.y, c0.z, c0.w, c1v.x, c1v.y, c1v.z, c1v.w};
    float csum[8] = {0, 0, 0, 0, 0, 0, 0, 0};
    float csq[8] = {0, 0, 0, 0, 0, 0, 0, 0};
#pragma unroll
    for (int i = 0; i < 8; i++) {
        int r = ty * 8 + i;
        int gr = row0 + r;
        if (gr < nrows) {
            float o[8];
#pragma unroll
            for (int j = 0; j < 8; j++) {
                o[j] = sO[r * 132 + tx * 8 + j] + bias[j] + sX[r * 132 + tx * 8 + j];
                csum[j] += o[j];
                csq[j] += o[j] * o[j];
            }
            *(float4*)(xout + (size_t)gr * 128 + tx * 8) = make_float4(o[0], o[1], o[2], o[3]);
            *(float4*)(xout + (size_t)gr * 128 + tx * 8 + 4) = make_float4(o[4], o[5], o[6], o[7]);
        }
    }
#pragma unroll
    for (int j = 0; j < 8; j++) {
        atomicAdd(&sCS[tx * 8 + j], csum[j]);
        atomicAdd(&sCQ[tx * 8 + j], csq[j]);
    }
    __syncthreads();
    if (tid < 128) {
        atomicAdd(&g_stats[statOff + tid], sCS[tid]);
        atomicAdd(&g_stats[statOff + 128 + tid], sCQ[tid]);
    }
}

// ---------------- final BN (elementwise) ----------------
__global__ void k_bnout(const float* x, int bnOff, const float* gam, const float* bet,
                        float* o, int nrows) {
    const float* mean = g_bnp + bnOff;
    const float* istd = g_bnp + bnOff + 128;
    int idx = blockIdx.x * blockDim.x + threadIdx.x;
    int stride = gridDim.x * blockDim.x;
    int total = nrows * 32;  // float4 units
    for (int i = idx; i < total; i += stride) {
        int c = (i & 31) << 2;
        float4 v = *(const float4*)(x + (size_t)i * 4);
        float4 r;
        r.x = (v.x - mean[c + 0]) * istd[c + 0] * gam[c + 0] + bet[c + 0];
        r.y = (v.y - mean[c + 1]) * istd[c + 1] * gam[c + 1] + bet[c + 1];
        r.z = (v.z - mean[c + 2]) * istd[c + 2] * gam[c + 2] + bet[c + 2];
        r.w = (v.w - mean[c + 3]) * istd[c + 3] * gam[c + 3] + bet[c + 3];
        *(float4*)(o + (size_t)i * 4) = r;
    }
}

// ---------------- launch ----------------
extern "C" void kernel_launch(void* const* d_in, const int* in_sizes, int n_in,
                              void* d_out, int out_size) {
    const float* h = (const float*)d_in[0];
    const float* e = (const float*)d_in[1];
    const int* src = (const int*)d_in[2];
    const int* dst = (const int*)d_in[3];
    const float* Wq = (const float*)d_in[4];
    const float* Wk = (const float*)d_in[5];
    const float* Wv = (const float*)d_in[6];
    const float* We = (const float*)d_in[7];
    const float* Wo_h = (const float*)d_in[8];
    const float* bo_h = (const float*)d_in[9];
    const float* Wo_e = (const float*)d_in[10];
    const float* bo_e = (const float*)d_in[11];
    const float* g1h = (const float*)d_in[12];
    const float* b1h = (const float*)d_in[13];
    const float* g1e = (const float*)d_in[14];
    const float* b1e = (const float*)d_in[15];
    const float* Wf1h = (const float*)d_in[16];
    const float* bf1h = (const float*)d_in[17];
    const float* Wf2h = (const float*)d_in[18];
    const float* bf2h = (const float*)d_in[19];
    const float* Wf1e = (const float*)d_in[20];
    const float* bf1e = (const float*)d_in[21];
    const float* Wf2e = (const float*)d_in[22];
    const float* bf2e = (const float*)d_in[23];
    const float* g2h = (const float*)d_in[24];
    const float* b2h = (const float*)d_in[25];
    const float* g2e = (const float*)d_in[26];
    const float* b2e = (const float*)d_in[27];
    float* out = (float*)d_out;
    float* out_e = out + (size_t)NN * D;

    float *p_hh, *p_h2, *p_ee;
    cudaGetSymbolAddress((void**)&p_hh, g_hh);
    cudaGetSymbolAddress((void**)&p_h2, g_h2);
    cudaGetSymbolAddress((void**)&p_ee, g_ee);

    const int smA = (128 * 132 + 128 * 128 + 256) * 4;
    const int sm1 = (64 * 132 * 3 + 128 * 136 + 512 + 256 + 128) * 4;
    const int smF = (128 * 132 + 128 * 72 + 128 * 68 + 64 * 136 + 256) * 4;
    cudaFuncSetAttribute(k_qkv, cudaFuncAttributeMaxDynamicSharedMemorySize, smA);
    cudaFuncSetAttribute(k_nattn, cudaFuncAttributeMaxDynamicSharedMemorySize, smA);
    cudaFuncSetAttribute(k_edge1, cudaFuncAttributeMaxDynamicSharedMemorySize, sm1);
    cudaFuncSetAttribute(k_ffn, cudaFuncAttributeMaxDynamicSharedMemorySize, smF);

    const int NBLK = (NN + 127) / 128;  // 391

    k_zero<<<2048, 256>>>();
    k_qkv<<<NBLK, 256, smA>>>(h, Wq, Wk, Wv);
    k_edge1<<<NE / 64, 256, sm1>>>(e, src, dst, We, Wo_e, bo_e);
    k_nattn<<<NBLK, 256, smA>>>(h, Wo_h, bo_h);
    k_finalize<<<1, 128>>>(0, (float)NE, 0);      // bn1e
    k_finalize<<<1, 128>>>(256, (float)NN, 256);  // bn1h
    k_ffn<<<NE / 128, 256, smF>>>(p_ee, out_e, 0, g1e, b1e, Wf1e, bf1e, Wf2e, bf2e, 512, NE);
    k_ffn<<<NBLK, 256, smF>>>(p_hh, p_h2, 256, g1h, b1h, Wf1h, bf1h, Wf2h, bf2h, 768, NN);
    k_finalize<<<1, 128>>>(512, (float)NE, 512);  // bn2e
    k_finalize<<<1, 128>>>(768, (float)NN, 768);  // bn2h
    k_bnout<<<2960, 256>>>(p_h2, 768, g2h, b2h, out, NN);
    k_bnout<<<2960, 256>>>(out_e, 512, g2e, b2e, out_e, NE);
}

// round 8
// speedup vs baseline: 1.6164x; 1.1040x over previous
#include <cuda_runtime.h>
#include <math.h>
#include <stdint.h>

#define NN 50000
#define NE 640000
#define D 128

// ---------------- scratch (device globals; no cudaMalloc allowed) ----------------
__device__ float g_Qh[NN * D];
__device__ float g_Kh[NN * D];
__device__ float g_Vh[NN * D];
__device__ float g_wV[NN * D];
__device__ float g_z[NN * 8];
__device__ float g_hh[NN * D];
__device__ float g_h2[NN * D];
__device__ float g_ee[NE * D];
__device__ float g_stats[8 * 128];
__device__ float g_bnp[8 * 128];

// ---------------- tf32 mma helpers ----------------
__device__ __forceinline__ uint32_t f2tf(float x) {
    uint32_t r;
    asm("cvt.rna.tf32.f32 %0, %1;" : "=r"(r) : "f"(x));
    return r;
}
__device__ __forceinline__ float f2tf_f(float x) { return __uint_as_float(f2tf(x)); }

__device__ __forceinline__ void mma8(float c[4], const uint32_t a[4], uint32_t b0, uint32_t b1) {
    asm volatile(
        "mma.sync.aligned.m16n8k8.row.col.f32.tf32.tf32.f32 "
        "{%0,%1,%2,%3}, {%4,%5,%6,%7}, {%8,%9}, {%0,%1,%2,%3};"
        : "+f"(c[0]), "+f"(c[1]), "+f"(c[2]), "+f"(c[3])
        : "r"(a[0]), "r"(a[1]), "r"(a[2]), "r"(a[3]), "r"(b0), "r"(b1));
}

__device__ __forceinline__ void red4(float* p, float x, float y, float z, float w) {
    asm volatile("red.global.add.v4.f32 [%0], {%1,%2,%3,%4};"
                 :: "l"(p), "f"(x), "f"(y), "f"(z), "f"(w) : "memory");
}

// ---------------- zero accumulators ----------------
__global__ void k_zero() {
    int idx = blockIdx.x * blockDim.x + threadIdx.x;
    int stride = gridDim.x * blockDim.x;
    const int nwv = NN * D, nz = NN * 8, nst = 8 * 128;
    for (int i = idx; i < nwv; i += stride) g_wV[i] = 0.f;
    for (int i = idx; i < nz; i += stride) g_z[i] = 0.f;
    for (int i = idx; i < nst; i += stride) g_stats[i] = 0.f;
}

// ---------------- Q/K/V GEMMs (FFMA; small share of total flops) ----------------
__global__ __launch_bounds__(256, 1) void k_qkv(const float* __restrict__ h,
                                                const float* __restrict__ Wq,
                                                const float* __restrict__ Wk,
                                                const float* __restrict__ Wv) {
    extern __shared__ float sm[];
    float* sA = sm;              // 128 x 132
    float* sB = sm + 128 * 132;  // 128 x 128
    const int tid = threadIdx.x, tx = tid & 15, ty = tid >> 4;
    const int row0 = blockIdx.x * 128;

    for (int i = tid; i < 128 * 32; i += 256) {
        int r = i >> 5, c4 = (i & 31) << 2;
        float4 v = make_float4(0.f, 0.f, 0.f, 0.f);
        if (row0 + r < NN) v = *(const float4*)(h + (row0 + r) * D + c4);
        *(float4*)(sA + r * 132 + c4) = v;
    }

    for (int wsel = 0; wsel < 3; wsel++) {
        const float* W = (wsel == 0) ? Wq : (wsel == 1) ? Wk : Wv;
        float* outp = (wsel == 0) ? g_Qh : (wsel == 1) ? g_Kh : g_Vh;
        __syncthreads();
        for (int i = tid; i < 128 * 32; i += 256) {
            int r = i >> 5, c4 = (i & 31) << 2;
            *(float4*)(sB + r * 128 + c4) = *(const float4*)(W + r * 128 + c4);
        }
        __syncthreads();

        float acc[8][8];
#pragma unroll
        for (int i = 0; i < 8; i++)
#pragma unroll
            for (int j = 0; j < 8; j++) acc[i][j] = 0.f;

#pragma unroll 1
        for (int k = 0; k < 128; k += 4) {
            float4 a[8];
#pragma unroll
            for (int i = 0; i < 8; i++) a[i] = *(const float4*)(sA + (ty * 8 + i) * 132 + k);
#pragma unroll
            for (int kk = 0; kk < 4; kk++) {
                float4 b0 = *(const float4*)(sB + (k + kk) * 128 + tx * 8);
                float4 b1 = *(const float4*)(sB + (k + kk) * 128 + tx * 8 + 4);
#pragma unroll
                for (int i = 0; i < 8; i++) {
                    float av = (kk == 0) ? a[i].x : (kk == 1) ? a[i].y : (kk == 2) ? a[i].z : a[i].w;
                    acc[i][0] += av * b0.x; acc[i][1] += av * b0.y;
                    acc[i][2] += av * b0.z; acc[i][3] += av * b0.w;
                    acc[i][4] += av * b1.x; acc[i][5] += av * b1.y;
                    acc[i][6] += av * b1.z; acc[i][7] += av * b1.w;
                }
            }
        }
#pragma unroll
        for (int i = 0; i < 8; i++) {
            int gr = row0 + ty * 8 + i;
            if (gr < NN) {
                *(float4*)(outp + gr * 128 + tx * 8) =
                    make_float4(acc[i][0], acc[i][1], acc[i][2], acc[i][3]);
                *(float4*)(outp + gr * 128 + tx * 8 + 4) =
                    make_float4(acc[i][4], acc[i][5], acc[i][6], acc[i][7]);
            }
        }
    }
}

// ---------------- fused edge kernel (tensor-core tf32 GEMMs) ----------------
__global__ __launch_bounds__(256, 1) void k_edge1(const float* __restrict__ e,
                                                  const int* __restrict__ src,
                                                  const int* __restrict__ dst,
                                                  const float* __restrict__ We,
                                                  const float* __restrict__ Wo_e,
                                                  const float* __restrict__ bo_e) {
    extern __shared__ float sm[];
    float* sE = sm;                    // 64 x 132  (e tile, PRE-CONVERTED tf32)
    float* sS = sE + 64 * 132;         // 64 x 132  (P fp32 -> score fp32 -> tf32)
    float* sO = sS + 64 * 132;         // 64 x 132  (GEMM2 out staging)
    float* sW = sO + 64 * 132;         // 128 x 136 (tf32 weights)
    float* swv = sW + 128 * 136;       // 64 x 8
    float* sCS = swv + 512;            // 128
    float* sCQ = sCS + 128;            // 128
    int* sSrc = (int*)(sCQ + 128);     // 64
    int* sDst = sSrc + 64;             // 64

    const int tid = threadIdx.x;
    const int lane = tid & 31, wid = tid >> 5;
    const int g = lane >> 2, q = lane & 3;
    const int wm = wid >> 2, wn = wid & 3;   // warp tile: 32 rows x 32 cols
    const int nc0 = wn * 32;
    const int row0 = blockIdx.x * 64;

    for (int i = tid; i < 64 * 32; i += 256) {
        int r = i >> 5, c4 = (i & 31) << 2;
        float4 v = *(const float4*)(e + (row0 + r) * D + c4);
        sE[r * 132 + c4 + 0] = f2tf_f(v.x);
        sE[r * 132 + c4 + 1] = f2tf_f(v.y);
        sE[r * 132 + c4 + 2] = f2tf_f(v.z);
        sE[r * 132 + c4 + 3] = f2tf_f(v.w);
    }
    for (int i = tid; i < 128 * 32; i += 256) {
        int r = i >> 5, c4 = (i & 31) << 2;
        float4 w = *(const float4*)(We + r * 128 + c4);
        sW[r * 136 + c4 + 0] = f2tf_f(w.x);
        sW[r * 136 + c4 + 1] = f2tf_f(w.y);
        sW[r * 136 + c4 + 2] = f2tf_f(w.z);
        sW[r * 136 + c4 + 3] = f2tf_f(w.w);
    }
    if (tid < 64) { sSrc[tid] = src[row0 + tid]; sDst[tid] = dst[row0 + tid]; }
    if (tid < 128) { sCS[tid] = 0.f; sCQ[tid] = 0.f; }
    __syncthreads();

    // GEMM1: P = e @ We   (warp: 2 m-tiles x 4 n-tiles of m16n8k8)
    {
        float c1[2][4][4];
#pragma unroll
        for (int m = 0; m < 2; m++)
#pragma unroll
            for (int n = 0; n < 4; n++)
#pragma unroll
                for (int j = 0; j < 4; j++) c1[m][n][j] = 0.f;

#pragma unroll 2
        for (int k0 = 0; k0 < 128; k0 += 8) {
            uint32_t a[2][4];
#pragma unroll
            for (int m = 0; m < 2; m++) {
                int rr = wm * 32 + m * 16;
                a[m][0] = __float_as_uint(sE[(rr + g) * 132 + k0 + q]);
                a[m][1] = __float_as_uint(sE[(rr + g + 8) * 132 + k0 + q]);
                a[m][2] = __float_as_uint(sE[(rr + g) * 132 + k0 + q + 4]);
                a[m][3] = __float_as_uint(sE[(rr + g + 8) * 132 + k0 + q + 4]);
            }
#pragma unroll
            for (int n = 0; n < 4; n++) {
                uint32_t b0 = __float_as_uint(sW[(k0 + q) * 136 + nc0 + n * 8 + g]);
                uint32_t b1 = __float_as_uint(sW[(k0 + q + 4) * 136 + nc0 + n * 8 + g]);
                mma8(c1[0][n], a[0], b0, b1);
                mma8(c1[1][n], a[1], b0, b1);
            }
        }
#pragma unroll
        for (int m = 0; m < 2; m++)
#pragma unroll
            for (int n = 0; n < 4; n++) {
                int r0 = wm * 32 + m * 16 + g, r1 = r0 + 8;
                int cc = nc0 + n * 8 + 2 * q;
                sS[r0 * 132 + cc] = c1[m][n][0];
                sS[r0 * 132 + cc + 1] = c1[m][n][1];
                sS[r1 * 132 + cc] = c1[m][n][2];
                sS[r1 * 132 + cc + 1] = c1[m][n][3];
            }
    }
    __syncthreads();

    // score = P * Kh[src] * Qh[dst] / 4  (in place, fp32)
    for (int i = tid; i < 64 * 32; i += 256) {
        int r = i >> 5, c4 = (i & 31) << 2;
        int s = sSrc[r], d = sDst[r];
        float4 p = *(float4*)(sS + r * 132 + c4);
        float4 kv = *(const float4*)(g_Kh + s * 128 + c4);
        float4 qv = *(const float4*)(g_Qh + d * 128 + c4);
        p.x *= kv.x * qv.x * 0.25f;
        p.y *= kv.y * qv.y * 0.25f;
        p.z *= kv.z * qv.z * 0.25f;
        p.w *= kv.w * qv.w * 0.25f;
        *(float4*)(sS + r * 132 + c4) = p;
    }
    __syncthreads();

    // per-head weights + z segment-sum (fp32 score); refill sW with Wo_e (tf32)
    for (int idx = tid; idx < 64 * 8; idx += 256) {
        int r = idx >> 3, hd = idx & 7;
        float ssum = 0.f;
#pragma unroll
        for (int t = 0; t < 16; t++) ssum += sS[r * 132 + hd * 16 + t];
        ssum = fminf(fmaxf(ssum, -5.f), 5.f);
        float wv = __expf(ssum);
        swv[idx] = wv;
        atomicAdd(&g_z[sDst[r] * 8 + hd], wv);
    }
    for (int i = tid; i < 128 * 32; i += 256) {
        int r = i >> 5, c4 = (i & 31) << 2;
        float4 w = *(const float4*)(Wo_e + r * 128 + c4);
        sW[r * 136 + c4 + 0] = f2tf_f(w.x);
        sW[r * 136 + c4 + 1] = f2tf_f(w.y);
        sW[r * 136 + c4 + 2] = f2tf_f(w.z);
        sW[r * 136 + c4 + 3] = f2tf_f(w.w);
    }
    __syncthreads();

    // wV segment-sum (vectorized red) + fold-in tf32 conversion of score
    for (int idx = tid; idx < 64 * 32; idx += 256) {
        int r = idx >> 5, c4 = (idx & 31) << 2;
        float wgt = swv[r * 8 + (c4 >> 4)];
        float4 vv = *(const float4*)(g_Vh + sSrc[r] * 128 + c4);
        red4(&g_wV[sDst[r] * 128 + c4], vv.x * wgt, vv.y * wgt, vv.z * wgt, vv.w * wgt);
        float4 sc = *(float4*)(sS + r * 132 + c4);
        sc.x = f2tf_f(sc.x);
        sc.y = f2tf_f(sc.y);
        sc.z = f2tf_f(sc.z);
        sc.w = f2tf_f(sc.w);
        *(float4*)(sS + r * 132 + c4) = sc;
    }
    __syncthreads();

    // GEMM2: ee_pre = score @ Wo_e
    {
        float c2[2][4][4];
#pragma unroll
        for (int m = 0; m < 2; m++)
#pragma unroll
            for (int n = 0; n < 4; n++)
#pragma unroll
                for (int j = 0; j < 4; j++) c2[m][n][j] = 0.f;

#pragma unroll 2
        for (int k0 = 0; k0 < 128; k0 += 8) {
            uint32_t a[2][4];
#pragma unroll
            for (int m = 0; m < 2; m++) {
                int rr = wm * 32 + m * 16;
                a[m][0] = __float_as_uint(sS[(rr + g) * 132 + k0 + q]);
                a[m][1] = __float_as_uint(sS[(rr + g + 8) * 132 + k0 + q]);
                a[m][2] = __float_as_uint(sS[(rr + g) * 132 + k0 + q + 4]);
                a[m][3] = __float_as_uint(sS[(rr + g + 8) * 132 + k0 + q + 4]);
            }
#pragma unroll
            for (int n = 0; n < 4; n++) {
                uint32_t b0 = __float_as_uint(sW[(k0 + q) * 136 + nc0 + n * 8 + g]);
                uint32_t b1 = __float_as_uint(sW[(k0 + q + 4) * 136 + nc0 + n * 8 + g]);
                mma8(c2[0][n], a[0], b0, b1);
                mma8(c2[1][n], a[1], b0, b1);
            }
        }
#pragma unroll
        for (int m = 0; m < 2; m++)
#pragma unroll
            for (int n = 0; n < 4; n++) {
                int r0 = wm * 32 + m * 16 + g, r1 = r0 + 8;
                int cc = nc0 + n * 8 + 2 * q;
                sO[r0 * 132 + cc] = c2[m][n][0];
                sO[r0 * 132 + cc + 1] = c2[m][n][1];
                sO[r1 * 132 + cc] = c2[m][n][2];
                sO[r1 * 132 + cc + 1] = c2[m][n][3];
            }
    }
    __syncthreads();

    // epilogue: bias + residual (re-read e fp32 from global) + store + stats
    const int tx = tid & 15, ty = tid >> 4;
    float4 bb0 = *(const float4*)(bo_e + tx * 8);
    float4 bb1 = *(const float4*)(bo_e + tx * 8 + 4);
    float bias[8] = {bb0.x, bb0.y, bb0.z, bb0.w, bb1.x, bb1.y, bb1.z, bb1.w};
    float csum[8] = {0, 0, 0, 0, 0, 0, 0, 0};
    float csq[8] = {0, 0, 0, 0, 0, 0, 0, 0};
#pragma unroll
    for (int i = 0; i < 4; i++) {
        int r = ty * 4 + i;
        float4 e0 = *(const float4*)(e + (row0 + r) * D + tx * 8);
        float4 e1 = *(const float4*)(e + (row0 + r) * D + tx * 8 + 4);
        float ev[8] = {e0.x, e0.y, e0.z, e0.w, e1.x, e1.y, e1.z, e1.w};
        float o[8];
#pragma unroll
        for (int j = 0; j < 8; j++) {
            o[j] = sO[r * 132 + tx * 8 + j] + bias[j] + ev[j];
            csum[j] += o[j];
            csq[j] += o[j] * o[j];
        }
        *(float4*)(g_ee + (row0 + r) * 128 + tx * 8) = make_float4(o[0], o[1], o[2], o[3]);
        *(float4*)(g_ee + (row0 + r) * 128 + tx * 8 + 4) = make_float4(o[4], o[5], o[6], o[7]);
    }
#pragma unroll
    for (int j = 0; j < 8; j++) {
        atomicAdd(&sCS[tx * 8 + j], csum[j]);
        atomicAdd(&sCQ[tx * 8 + j], csq[j]);
    }
    __syncthreads();
    if (tid < 128) {
        atomicAdd(&g_stats[0 * 128 + tid], sCS[tid]);
        atomicAdd(&g_stats[1 * 128 + tid], sCQ[tid]);
    }
}

// ---------------- node attention output (FFMA; small) ----------------
__global__ __launch_bounds__(256, 1) void k_nattn(const float* __restrict__ h,
                                                  const float* __restrict__ Wo_h,
                                                  const float* __restrict__ bo_h) {
    extern __shared__ float sm[];
    float* sA = sm;                   // 128 x 132
    float* sB = sm + 128 * 132;       // 128 x 128
    float* sCS = sB + 128 * 128;      // 128
    float* sCQ = sCS + 128;           // 128
    const int tid = threadIdx.x, tx = tid & 15, ty = tid >> 4;
    const int row0 = blockIdx.x * 128;

    for (int i = tid; i < 128 * 128; i += 256) {
        int r = i >> 7, c = i & 127;
        int gr = row0 + r;
        float v = 0.f;
        if (gr < NN) {
            float zz = g_z[gr * 8 + (c >> 4)];
            v = g_wV[gr * 128 + c] / (zz + 1e-6f);
        }
        sA[r * 132 + c] = v;
    }
    for (int i = tid; i < 128 * 32; i += 256) {
        int r = i >> 5, c4 = (i & 31) << 2;
        *(float4*)(sB + r * 128 + c4) = *(const float4*)(Wo_h + r * 128 + c4);
    }
    if (tid < 128) { sCS[tid] = 0.f; sCQ[tid] = 0.f; }
    __syncthreads();

    float acc[8][8];
#pragma unroll
    for (int i = 0; i < 8; i++)
#pragma unroll
        for (int j = 0; j < 8; j++) acc[i][j] = 0.f;

#pragma unroll 1
    for (int k = 0; k < 128; k += 4) {
        float4 a[8];
#pragma unroll
        for (int i = 0; i < 8; i++) a[i] = *(const float4*)(sA + (ty * 8 + i) * 132 + k);
#pragma unroll
        for (int kk = 0; kk < 4; kk++) {
            float4 b0 = *(const float4*)(sB + (k + kk) * 128 + tx * 8);
            float4 b1 = *(const float4*)(sB + (k + kk) * 128 + tx * 8 + 4);
#pragma unroll
            for (int i = 0; i < 8; i++) {
                float av = (kk == 0) ? a[i].x : (kk == 1) ? a[i].y : (kk == 2) ? a[i].z : a[i].w;
                acc[i][0] += av * b0.x; acc[i][1] += av * b0.y;
                acc[i][2] += av * b0.z; acc[i][3] += av * b0.w;
                acc[i][4] += av * b1.x; acc[i][5] += av * b1.y;
                acc[i][6] += av * b1.z; acc[i][7] += av * b1.w;
            }
        }
    }

    float4 bb0 = *(const float4*)(bo_h + tx * 8);
    float4 bb1 = *(const float4*)(bo_h + tx * 8 + 4);
    float csum[8] = {0, 0, 0, 0, 0, 0, 0, 0};
    float csq[8] = {0, 0, 0, 0, 0, 0, 0, 0};
#pragma unroll
    for (int i = 0; i < 8; i++) {
        int gr = row0 + ty * 8 + i;
        if (gr < NN) {
            float4 r0 = *(const float4*)(h + gr * 128 + tx * 8);
            float4 r1 = *(const float4*)(h + gr * 128 + tx * 8 + 4);
            float o[8];
            o[0] = acc[i][0] + bb0.x + r0.x; o[1] = acc[i][1] + bb0.y + r0.y;
            o[2] = acc[i][2] + bb0.z + r0.z; o[3] = acc[i][3] + bb0.w + r0.w;
            o[4] = acc[i][4] + bb1.x + r1.x; o[5] = acc[i][5] + bb1.y + r1.y;
            o[6] = acc[i][6] + bb1.z + r1.z; o[7] = acc[i][7] + bb1.w + r1.w;
            *(float4*)(g_hh + gr * 128 + tx * 8) = make_float4(o[0], o[1], o[2], o[3]);
            *(float4*)(g_hh + gr * 128 + tx * 8 + 4) = make_float4(o[4], o[5], o[6], o[7]);
#pragma unroll
            for (int j = 0; j < 8; j++) { csum[j] += o[j]; csq[j] += o[j] * o[j]; }
        }
    }
#pragma unroll
    for (int j = 0; j < 8; j++) {
        atomicAdd(&sCS[tx * 8 + j], csum[j]);
        atomicAdd(&sCQ[tx * 8 + j], csq[j]);
    }
    __syncthreads();
    if (tid < 128) {
        atomicAdd(&g_stats[2 * 128 + tid], sCS[tid]);
        atomicAdd(&g_stats[3 * 128 + tid], sCQ[tid]);
    }
}

// ---------------- finalize BN stats ----------------
__global__ void k_finalize(int statOff, float cnt, int bnOff) {
    int c = threadIdx.x;  // 128
    float m = g_stats[statOff + c] / cnt;
    float var = g_stats[statOff + 128 + c] / cnt - m * m;
    g_bnp[bnOff + c] = m;
    g_bnp[bnOff + 128 + c] = rsqrtf(var + 1e-5f);
}

// ---------------- fused BN1 + FFN + residual + stats2 (tensor-core tf32) ----------------
__global__ __launch_bounds__(256, 1) void k_ffn(const float* __restrict__ xin, float* xout,
                                                int bnOff,
                                                const float* __restrict__ gam,
                                                const float* __restrict__ bet,
                                                const float* __restrict__ Wa,
                                                const float* __restrict__ ba,
                                                const float* __restrict__ Wb,
                                                const float* __restrict__ bb2,
                                                int statOff, int nrows) {
    extern __shared__ float sm[];
    float* sX = sm;                      // 128 x 132 (post-BN input, PRE-CONVERTED tf32)
    float* sW1 = sX + 128 * 132;         // 128 x 72 (tf32 W1 chunk)
    float* sY = sW1 + 128 * 72;          // 128 x 68 (tf32 relu output)
    float* sW2 = sY + 128 * 68;          // 64 x 136 (tf32 W2 chunk)
    float* sCS = sW2 + 64 * 136;         // 128
    float* sCQ = sCS + 128;              // 128
    float* sO = sW1;                     // overlay: 128 x 132 output staging (after loops)

    const int tid = threadIdx.x;
    const int lane = tid & 31, wid = tid >> 5;
    const int g = lane >> 2, q = lane & 3;
    const int wm = wid >> 1, wn = wid & 1;
    const int row0 = blockIdx.x * 128;
    const float* mean = g_bnp + bnOff;
    const float* istd = g_bnp + bnOff + 128;

    for (int i = tid; i < 128 * 128; i += 256) {
        int r = i >> 7, c = i & 127;
        int gr = row0 + r;
        float v = 0.f;
        if (gr < nrows) v = (xin[(size_t)gr * 128 + c] - mean[c]) * istd[c] * gam[c] + bet[c];
        sX[r * 132 + c] = f2tf_f(v);
    }
    if (tid < 128) { sCS[tid] = 0.f; sCQ[tid] = 0.f; }

    float accO[2][8][4];   // rows wm*32 + m*16, cols wn*64 + n*8
#pragma unroll
    for (int m = 0; m < 2; m++)
#pragma unroll
        for (int n = 0; n < 8; n++)
#pragma unroll
            for (int j = 0; j < 4; j++) accO[m][n][j] = 0.f;

    for (int ch = 0; ch < 4; ch++) {
        __syncthreads();
        for (int i = tid; i < 128 * 16; i += 256) {
            int k = i >> 4, c4 = (i & 15) << 2;
            float4 w = *(const float4*)(Wa + k * 256 + ch * 64 + c4);
            sW1[k * 72 + c4 + 0] = f2tf_f(w.x);
            sW1[k * 72 + c4 + 1] = f2tf_f(w.y);
            sW1[k * 72 + c4 + 2] = f2tf_f(w.z);
            sW1[k * 72 + c4 + 3] = f2tf_f(w.w);
        }
        for (int i = tid; i < 64 * 32; i += 256) {
            int k = i >> 5, c4 = (i & 31) << 2;
            float4 w = *(const float4*)(Wb + (ch * 64 + k) * 128 + c4);
            sW2[k * 136 + c4 + 0] = f2tf_f(w.x);
            sW2[k * 136 + c4 + 1] = f2tf_f(w.y);
            sW2[k * 136 + c4 + 2] = f2tf_f(w.z);
            sW2[k * 136 + c4 + 3] = f2tf_f(w.w);
        }
        __syncthreads();

        // GEMM1: y = relu(sX @ W1chunk + b1chunk)  (warp: 32 rows x 32 cols)
        float c1[2][4][4];
#pragma unroll
        for (int m = 0; m < 2; m++)
#pragma unroll
            for (int n = 0; n < 4; n++)
#pragma unroll
                for (int j = 0; j < 4; j++) c1[m][n][j] = 0.f;

        const int nb = wn * 32;
#pragma unroll 2
        for (int k0 = 0; k0 < 128; k0 += 8) {
            uint32_t a[2][4];
#pragma unroll
            for (int m = 0; m < 2; m++) {
                int rr = wm * 32 + m * 16;
                a[m][0] = __float_as_uint(sX[(rr + g) * 132 + k0 + q]);
                a[m][1] = __float_as_uint(sX[(rr + g + 8) * 132 + k0 + q]);
                a[m][2] = __float_as_uint(sX[(rr + g) * 132 + k0 + q + 4]);
                a[m][3] = __float_as_uint(sX[(rr + g + 8) * 132 + k0 + q + 4]);
            }
#pragma unroll
            for (int n = 0; n < 4; n++) {
                uint32_t b0 = __float_as_uint(sW1[(k0 + q) * 72 + nb + n * 8 + g]);
                uint32_t b1 = __float_as_uint(sW1[(k0 + q + 4) * 72 + nb + n * 8 + g]);
                mma8(c1[0][n], a[0], b0, b1);
                mma8(c1[1][n], a[1], b0, b1);
            }
        }
        // bias + relu -> sY (pre-converted tf32)
#pragma unroll
        for (int m = 0; m < 2; m++)
#pragma unroll
            for (int n = 0; n < 4; n++) {
                int cc = nb + n * 8 + 2 * q;
                float bv0 = ba[ch * 64 + cc], bv1 = ba[ch * 64 + cc + 1];
                int r0 = wm * 32 + m * 16 + g, r1 = r0 + 8;
                sY[r0 * 68 + cc] = f2tf_f(fmaxf(c1[m][n][0] + bv0, 0.f));
                sY[r0 * 68 + cc + 1] = f2tf_f(fmaxf(c1[m][n][1] + bv1, 0.f));
                sY[r1 * 68 + cc] = f2tf_f(fmaxf(c1[m][n][2] + bv0, 0.f));
                sY[r1 * 68 + cc + 1] = f2tf_f(fmaxf(c1[m][n][3] + bv1, 0.f));
            }
        __syncthreads();

        // GEMM2 accumulate: out += y @ W2chunk  (warp: 32 rows x 64 cols)
#pragma unroll 2
        for (int k0 = 0; k0 < 64; k0 += 8) {
            uint32_t a[2][4];
#pragma unroll
            for (int m = 0; m < 2; m++) {
                int rr = wm * 32 + m * 16;
                a[m][0] = __float_as_uint(sY[(rr + g) * 68 + k0 + q]);
                a[m][1] = __float_as_uint(sY[(rr + g + 8) * 68 + k0 + q]);
                a[m][2] = __float_as_uint(sY[(rr + g) * 68 + k0 + q + 4]);
                a[m][3] = __float_as_uint(sY[(rr + g + 8) * 68 + k0 + q + 4]);
            }
#pragma unroll
            for (int n = 0; n < 8; n++) {
                uint32_t b0 = __float_as_uint(sW2[(k0 + q) * 136 + wn * 64 + n * 8 + g]);
                uint32_t b1 = __float_as_uint(sW2[(k0 + q + 4) * 136 + wn * 64 + n * 8 + g]);
                mma8(accO[0][n], a[0], b0, b1);
                mma8(accO[1][n], a[1], b0, b1);
            }
        }
    }
    __syncthreads();   // all warps done reading sW1/sY before overlay stores

    // stage output frags to sO
#pragma unroll
    for (int m = 0; m < 2; m++)
#pragma unroll
        for (int n = 0; n < 8; n++) {
            int r0 = wm * 32 + m * 16 + g, r1 = r0 + 8;
            int cc = wn * 64 + n * 8 + 2 * q;
            sO[r0 * 132 + cc] = accO[m][n][0];
            sO[r0 * 132 + cc + 1] = accO[m][n][1];
            sO[r1 * 132 + cc] = accO[m][n][2];
            sO[r1 * 132 + cc + 1] = accO[m][n][3];
        }
    __syncthreads();

    // epilogue: bias + residual (recompute BN fp32 from re-read xin) + store + stats
    const int tx = tid & 15, ty = tid >> 4;
    float4 c0 = *(const float4*)(bb2 + tx * 8);
    float4 c1v = *(const float4*)(bb2 + tx * 8 + 4);
    float bias[8] = {c0.x, c0.y, c0.z, c0.w, c1v.x, c1v.y, c1v.z, c1v.w};
    float mn[8], is_[8], gm[8], bt[8];
#pragma unroll
    for (int j = 0; j < 8; j++) {
        int c = tx * 8 + j;
        mn[j] = mean[c]; is_[j] = istd[c]; gm[j] = gam[c]; bt[j] = bet[c];
    }
    float csum[8] = {0, 0, 0, 0, 0, 0, 0, 0};
    float csq[8] = {0, 0, 0, 0, 0, 0, 0, 0};
#pragma unroll
    for (int i = 0; i < 8; i++) {
        int r = ty * 8 + i;
        int gr = row0 + r;
        if (gr < nrows) {
            float4 x0 = *(const float4*)(xin + (size_t)gr * 128 + tx * 8);
            float4 x1 = *(const float4*)(xin + (size_t)gr * 128 + tx * 8 + 4);
            float xv[8] = {x0.x, x0.y, x0.z, x0.w, x1.x, x1.y, x1.z, x1.w};
            float o[8];
#pragma unroll
            for (int j = 0; j < 8; j++) {
                float resid = (xv[j] - mn[j]) * is_[j] * gm[j] + bt[j];
                o[j] = sO[r * 132 + tx * 8 + j] + bias[j] + resid;
                csum[j] += o[j];
                csq[j] += o[j] * o[j];
            }
            *(float4*)(xout + (size_t)gr * 128 + tx * 8) = make_float4(o[0], o[1], o[2], o[3]);
            *(float4*)(xout + (size_t)gr * 128 + tx * 8 + 4) = make_float4(o[4], o[5], o[6], o[7]);
        }
    }
#pragma unroll
    for (int j = 0; j < 8; j++) {
        atomicAdd(&sCS[tx * 8 + j], csum[j]);
        atomicAdd(&sCQ[tx * 8 + j], csq[j]);
    }
    __syncthreads();
    if (tid < 128) {
        atomicAdd(&g_stats[statOff + tid], sCS[tid]);
        atomicAdd(&g_stats[statOff + 128 + tid], sCQ[tid]);
    }
}

// ---------------- final BN (elementwise) ----------------
__global__ void k_bnout(const float* x, int bnOff, const float* gam, const float* bet,
                        float* o, int nrows) {
    const float* mean = g_bnp + bnOff;
    const float* istd = g_bnp + bnOff + 128;
    int idx = blockIdx.x * blockDim.x + threadIdx.x;
    int stride = gridDim.x * blockDim.x;
    int total = nrows * 32;  // float4 units
    for (int i = idx; i < total; i += stride) {
        int c = (i & 31) << 2;
        float4 v = *(const float4*)(x + (size_t)i * 4);
        float4 r;
        r.x = (v.x - mean[c + 0]) * istd[c + 0] * gam[c + 0] + bet[c + 0];
        r.y = (v.y - mean[c + 1]) * istd[c + 1] * gam[c + 1] + bet[c + 1];
        r.z = (v.z - mean[c + 2]) * istd[c + 2] * gam[c + 2] + bet[c + 2];
        r.w = (v.w - mean[c + 3]) * istd[c + 3] * gam[c + 3] + bet[c + 3];
        *(float4*)(o + (size_t)i * 4) = r;
    }
}

// ---------------- launch ----------------
extern "C" void kernel_launch(void* const* d_in, const int* in_sizes, int n_in,
                              void* d_out, int out_size) {
    const float* h = (const float*)d_in[0];
    const float* e = (const float*)d_in[1];
    const int* src = (const int*)d_in[2];
    const int* dst = (const int*)d_in[3];
    const float* Wq = (const float*)d_in[4];
    const float* Wk = (const float*)d_in[5];
    const float* Wv = (const float*)d_in[6];
    const float* We = (const float*)d_in[7];
    const float* Wo_h = (const float*)d_in[8];
    const float* bo_h = (const float*)d_in[9];
    const float* Wo_e = (const float*)d_in[10];
    const float* bo_e = (const float*)d_in[11];
    const float* g1h = (const float*)d_in[12];
    const float* b1h = (const float*)d_in[13];
    const float* g1e = (const float*)d_in[14];
    const float* b1e = (const float*)d_in[15];
    const float* Wf1h = (const float*)d_in[16];
    const float* bf1h = (const float*)d_in[17];
    const float* Wf2h = (const float*)d_in[18];
    const float* bf2h = (const float*)d_in[19];
    const float* Wf1e = (const float*)d_in[20];
    const float* bf1e = (const float*)d_in[21];
    const float* Wf2e = (const float*)d_in[22];
    const float* bf2e = (const float*)d_in[23];
    const float* g2h = (const float*)d_in[24];
    const float* b2h = (const float*)d_in[25];
    const float* g2e = (const float*)d_in[26];
    const float* b2e = (const float*)d_in[27];
    float* out = (float*)d_out;
    float* out_e = out + (size_t)NN * D;

    float *p_hh, *p_h2, *p_ee;
    cudaGetSymbolAddress((void**)&p_hh, g_hh);
    cudaGetSymbolAddress((void**)&p_h2, g_h2);
    cudaGetSymbolAddress((void**)&p_ee, g_ee);

    const int smA = (128 * 132 + 128 * 128 + 256) * 4;
    const int sm1 = (64 * 132 * 3 + 128 * 136 + 512 + 256 + 128) * 4;
    const int smF = (128 * 132 + 128 * 72 + 128 * 68 + 64 * 136 + 256) * 4;
    cudaFuncSetAttribute(k_qkv, cudaFuncAttributeMaxDynamicSharedMemorySize, smA);
    cudaFuncSetAttribute(k_nattn, cudaFuncAttributeMaxDynamicSharedMemorySize, smA);
    cudaFuncSetAttribute(k_edge1, cudaFuncAttributeMaxDynamicSharedMemorySize, sm1);
    cudaFuncSetAttribute(k_ffn, cudaFuncAttributeMaxDynamicSharedMemorySize, smF);

    const int NBLK = (NN + 127) / 128;  // 391

    k_zero<<<2048, 256>>>();
    k_qkv<<<NBLK, 256, smA>>>(h, Wq, Wk, Wv);
    k_edge1<<<NE / 64, 256, sm1>>>(e, src, dst, We, Wo_e, bo_e);
    k_nattn<<<NBLK, 256, smA>>>(h, Wo_h, bo_h);
    k_finalize<<<1, 128>>>(0, (float)NE, 0);      // bn1e
    k_finalize<<<1, 128>>>(256, (float)NN, 256);  // bn1h
    k_ffn<<<NE / 128, 256, smF>>>(p_ee, out_e, 0, g1e, b1e, Wf1e, bf1e, Wf2e, bf2e, 512, NE);
    k_ffn<<<NBLK, 256, smF>>>(p_hh, p_h2, 256, g1h, b1h, Wf1h, bf1h, Wf2h, bf2h, 768, NN);
    k_finalize<<<1, 128>>>(512, (float)NE, 512);  // bn2e
    k_finalize<<<1, 128>>>(768, (float)NN, 768);  // bn2h
    k_bnout<<<2960, 256>>>(p_h2, 768, g2h, b2h, out, NN);
    k_bnout<<<2960, 256>>>(out_e, 512, g2e, b2e, out_e, NE);
}

// round 9
// speedup vs baseline: 1.7074x; 1.0563x over previous
#include <cuda_runtime.h>
#include <math.h>
#include <stdint.h>

#define NN 50000
#define NE 640000
#define D 128

// ---------------- scratch (device globals; no cudaMalloc allowed) ----------------
__device__ float g_Qh[NN * D];
__device__ float g_Kh[NN * D];
__device__ float g_Vh[NN * D];
__device__ float g_wV[NN * D];
__device__ float g_z[NN * 8];
__device__ float g_hh[NN * D];
__device__ float g_h2[NN * D];
__device__ float g_ee[NE * D];
__device__ float g_stats[8 * 128];
__device__ float g_bnp[8 * 128];
__device__ float g_tfw[229376];   // tf32 pre-converted weights

// offsets inside g_tfw
#define TQ  0
#define TK  16384
#define TV  32768
#define TE  49152
#define TOH 65536
#define TOE 81920
#define T1H 98304
#define T2H 131072
#define T1E 163840
#define T2E 196608

// ---------------- tf32 mma helpers ----------------
__device__ __forceinline__ uint32_t f2tf(float x) {
    uint32_t r;
    asm("cvt.rna.tf32.f32 %0, %1;" : "=r"(r) : "f"(x));
    return r;
}
__device__ __forceinline__ float f2tf_f(float x) { return __uint_as_float(f2tf(x)); }

__device__ __forceinline__ void mma8(float c[4], const uint32_t a[4], uint32_t b0, uint32_t b1) {
    asm volatile(
        "mma.sync.aligned.m16n8k8.row.col.f32.tf32.tf32.f32 "
        "{%0,%1,%2,%3}, {%4,%5,%6,%7}, {%8,%9}, {%0,%1,%2,%3};"
        : "+f"(c[0]), "+f"(c[1]), "+f"(c[2]), "+f"(c[3])
        : "r"(a[0]), "r"(a[1]), "r"(a[2]), "r"(a[3]), "r"(b0), "r"(b1));
}

__device__ __forceinline__ void red4(float* p, float x, float y, float z, float w) {
    asm volatile("red.global.add.v4.f32 [%0], {%1,%2,%3,%4};"
                 :: "l"(p), "f"(x), "f"(y), "f"(z), "f"(w) : "memory");
}

__device__ __forceinline__ void cpasync16(uint32_t s, const void* g) {
    asm volatile("cp.async.cg.shared.global [%0], [%1], 16;" :: "r"(s), "l"(g));
}

// ---------------- weight pre-conversion (tf32-rna, once per call) ----------------
__global__ void k_prep(const float* Wq, const float* Wk, const float* Wv, const float* We,
                       const float* Woh, const float* Woe, const float* W1h, const float* W2h,
                       const float* W1e, const float* W2e) {
    int i = blockIdx.x * blockDim.x + threadIdx.x;
    int stride = gridDim.x * blockDim.x;
    for (; i < 229376; i += stride) {
        float v;
        if (i < 16384) v = Wq[i];
        else if (i < 32768) v = Wk[i - 16384];
        else if (i < 49152) v = Wv[i - 32768];
        else if (i < 65536) v = We[i - 49152];
        else if (i < 81920) v = Woh[i - 65536];
        else if (i < 98304) v = Woe[i - 81920];
        else if (i < 131072) v = W1h[i - 98304];
        else if (i < 163840) v = W2h[i - 131072];
        else if (i < 196608) v = W1e[i - 163840];
        else v = W2e[i - 196608];
        g_tfw[i] = f2tf_f(v);
    }
}

// ---------------- zero accumulators ----------------
__global__ void k_zero() {
    int idx = blockIdx.x * blockDim.x + threadIdx.x;
    int stride = gridDim.x * blockDim.x;
    const int nwv = NN * D, nz = NN * 8, nst = 8 * 128;
    for (int i = idx; i < nwv; i += stride) g_wV[i] = 0.f;
    for (int i = idx; i < nz; i += stride) g_z[i] = 0.f;
    for (int i = idx; i < nst; i += stride) g_stats[i] = 0.f;
}

// ---------------- Q/K/V GEMMs (tf32 mma) ----------------
__global__ __launch_bounds__(256, 1) void k_qkv(const float* __restrict__ h) {
    extern __shared__ float sm[];
    float* sA = sm;                 // 128 x 132 (tf32 of h)
    float* sB = sA + 128 * 132;     // 128 x 136 (tf32 weights)
    float* sO = sB + 128 * 136;     // 128 x 132 (output staging)
    const int tid = threadIdx.x;
    const int lane = tid & 31, wid = tid >> 5;
    const int g = lane >> 2, q = lane & 3;
    const int wm = wid >> 1, wn = wid & 1;
    const int tx = tid & 15, ty = tid >> 4;
    const int row0 = blockIdx.x * 128;

    for (int i = tid; i < 128 * 32; i += 256) {
        int r = i >> 5, c4 = (i & 31) << 2;
        float4 v = make_float4(0.f, 0.f, 0.f, 0.f);
        if (row0 + r < NN) v = *(const float4*)(h + (row0 + r) * D + c4);
        sA[r * 132 + c4 + 0] = f2tf_f(v.x);
        sA[r * 132 + c4 + 1] = f2tf_f(v.y);
        sA[r * 132 + c4 + 2] = f2tf_f(v.z);
        sA[r * 132 + c4 + 3] = f2tf_f(v.w);
    }

    for (int wsel = 0; wsel < 3; wsel++) {
        const float* W = g_tfw + wsel * 16384;   // TQ, TK, TV
        float* outp = (wsel == 0) ? g_Qh : (wsel == 1) ? g_Kh : g_Vh;
        for (int i = tid; i < 128 * 32; i += 256) {
            int r = i >> 5, c4 = (i & 31) << 2;
            *(float4*)(sB + r * 136 + c4) = *(const float4*)(W + r * 128 + c4);
        }
        __syncthreads();

        float acc[2][8][4];
#pragma unroll
        for (int m = 0; m < 2; m++)
#pragma unroll
            for (int n = 0; n < 8; n++)
#pragma unroll
                for (int j = 0; j < 4; j++) acc[m][n][j] = 0.f;

#pragma unroll 2
        for (int k0 = 0; k0 < 128; k0 += 8) {
            uint32_t a[2][4];
#pragma unroll
            for (int m = 0; m < 2; m++) {
                int rr = wm * 32 + m * 16;
                a[m][0] = __float_as_uint(sA[(rr + g) * 132 + k0 + q]);
                a[m][1] = __float_as_uint(sA[(rr + g + 8) * 132 + k0 + q]);
                a[m][2] = __float_as_uint(sA[(rr + g) * 132 + k0 + q + 4]);
                a[m][3] = __float_as_uint(sA[(rr + g + 8) * 132 + k0 + q + 4]);
            }
#pragma unroll
            for (int n = 0; n < 8; n++) {
                uint32_t b0 = __float_as_uint(sB[(k0 + q) * 136 + wn * 64 + n * 8 + g]);
                uint32_t b1 = __float_as_uint(sB[(k0 + q + 4) * 136 + wn * 64 + n * 8 + g]);
                mma8(acc[0][n], a[0], b0, b1);
                mma8(acc[1][n], a[1], b0, b1);
            }
        }
#pragma unroll
        for (int m = 0; m < 2; m++)
#pragma unroll
            for (int n = 0; n < 8; n++) {
                int r0 = wm * 32 + m * 16 + g, r1 = r0 + 8;
                int cc = wn * 64 + n * 8 + 2 * q;
                sO[r0 * 132 + cc] = acc[m][n][0];
                sO[r0 * 132 + cc + 1] = acc[m][n][1];
                sO[r1 * 132 + cc] = acc[m][n][2];
                sO[r1 * 132 + cc + 1] = acc[m][n][3];
            }
        __syncthreads();

#pragma unroll
        for (int i = 0; i < 8; i++) {
            int gr = row0 + ty * 8 + i;
            if (gr < NN) {
                *(float4*)(outp + gr * 128 + tx * 8) = *(float4*)(sO + (ty * 8 + i) * 132 + tx * 8);
                *(float4*)(outp + gr * 128 + tx * 8 + 4) = *(float4*)(sO + (ty * 8 + i) * 132 + tx * 8 + 4);
            }
        }
    }
}

// ---------------- fused edge kernel (tensor-core tf32 GEMMs) ----------------
__global__ __launch_bounds__(256, 1) void k_edge1(const float* __restrict__ e,
                                                  const int* __restrict__ src,
                                                  const int* __restrict__ dst,
                                                  const float* __restrict__ bo_e) {
    extern __shared__ float sm[];
    float* sE = sm;                    // 64 x 132  (e tile, tf32)
    float* sS = sE + 64 * 132;         // 64 x 132  (P fp32 -> score fp32 -> tf32)
    float* sO = sS + 64 * 132;         // 64 x 132  (GEMM2 out staging)
    float* sW = sO + 64 * 132;         // 128 x 136 (tf32 weights)
    float* swv = sW + 128 * 136;       // 64 x 8
    float* sCS = swv + 512;            // 128
    float* sCQ = sCS + 128;            // 128
    int* sSrc = (int*)(sCQ + 128);     // 64
    int* sDst = sSrc + 64;             // 64

    const float* tfWe = g_tfw + TE;
    const float* tfWoe = g_tfw + TOE;

    const int tid = threadIdx.x;
    const int lane = tid & 31, wid = tid >> 5;
    const int g = lane >> 2, q = lane & 3;
    const int wm = wid >> 2, wn = wid & 3;   // warp tile: 32 rows x 32 cols
    const int nc0 = wn * 32;
    const int row0 = blockIdx.x * 64;

    for (int i = tid; i < 64 * 32; i += 256) {
        int r = i >> 5, c4 = (i & 31) << 2;
        float4 v = *(const float4*)(e + (row0 + r) * D + c4);
        sE[r * 132 + c4 + 0] = f2tf_f(v.x);
        sE[r * 132 + c4 + 1] = f2tf_f(v.y);
        sE[r * 132 + c4 + 2] = f2tf_f(v.z);
        sE[r * 132 + c4 + 3] = f2tf_f(v.w);
    }
    for (int i = tid; i < 128 * 32; i += 256) {
        int r = i >> 5, c4 = (i & 31) << 2;
        *(float4*)(sW + r * 136 + c4) = *(const float4*)(tfWe + r * 128 + c4);
    }
    if (tid < 64) { sSrc[tid] = src[row0 + tid]; sDst[tid] = dst[row0 + tid]; }
    if (tid < 128) { sCS[tid] = 0.f; sCQ[tid] = 0.f; }
    __syncthreads();

    // GEMM1: P = e @ We
    {
        float c1[2][4][4];
#pragma unroll
        for (int m = 0; m < 2; m++)
#pragma unroll
            for (int n = 0; n < 4; n++)
#pragma unroll
                for (int j = 0; j < 4; j++) c1[m][n][j] = 0.f;

#pragma unroll 2
        for (int k0 = 0; k0 < 128; k0 += 8) {
            uint32_t a[2][4];
#pragma unroll
            for (int m = 0; m < 2; m++) {
                int rr = wm * 32 + m * 16;
                a[m][0] = __float_as_uint(sE[(rr + g) * 132 + k0 + q]);
                a[m][1] = __float_as_uint(sE[(rr + g + 8) * 132 + k0 + q]);
                a[m][2] = __float_as_uint(sE[(rr + g) * 132 + k0 + q + 4]);
                a[m][3] = __float_as_uint(sE[(rr + g + 8) * 132 + k0 + q + 4]);
            }
#pragma unroll
            for (int n = 0; n < 4; n++) {
                uint32_t b0 = __float_as_uint(sW[(k0 + q) * 136 + nc0 + n * 8 + g]);
                uint32_t b1 = __float_as_uint(sW[(k0 + q + 4) * 136 + nc0 + n * 8 + g]);
                mma8(c1[0][n], a[0], b0, b1);
                mma8(c1[1][n], a[1], b0, b1);
            }
        }
#pragma unroll
        for (int m = 0; m < 2; m++)
#pragma unroll
            for (int n = 0; n < 4; n++) {
                int r0 = wm * 32 + m * 16 + g, r1 = r0 + 8;
                int cc = nc0 + n * 8 + 2 * q;
                sS[r0 * 132 + cc] = c1[m][n][0];
                sS[r0 * 132 + cc + 1] = c1[m][n][1];
                sS[r1 * 132 + cc] = c1[m][n][2];
                sS[r1 * 132 + cc + 1] = c1[m][n][3];
            }
    }
    __syncthreads();

    // score = P * Kh[src] * Qh[dst] / 4  (in place, fp32)
    for (int i = tid; i < 64 * 32; i += 256) {
        int r = i >> 5, c4 = (i & 31) << 2;
        int s = sSrc[r], d = sDst[r];
        float4 p = *(float4*)(sS + r * 132 + c4);
        float4 kv = *(const float4*)(g_Kh + s * 128 + c4);
        float4 qv = *(const float4*)(g_Qh + d * 128 + c4);
        p.x *= kv.x * qv.x * 0.25f;
        p.y *= kv.y * qv.y * 0.25f;
        p.z *= kv.z * qv.z * 0.25f;
        p.w *= kv.w * qv.w * 0.25f;
        *(float4*)(sS + r * 132 + c4) = p;
    }
    __syncthreads();

    // per-head weights + z segment-sum (fp32); refill sW with Wo_e
    for (int idx = tid; idx < 64 * 8; idx += 256) {
        int r = idx >> 3, hd = idx & 7;
        float ssum = 0.f;
#pragma unroll
        for (int t = 0; t < 16; t++) ssum += sS[r * 132 + hd * 16 + t];
        ssum = fminf(fmaxf(ssum, -5.f), 5.f);
        float wv = __expf(ssum);
        swv[idx] = wv;
        atomicAdd(&g_z[sDst[r] * 8 + hd], wv);
    }
    for (int i = tid; i < 128 * 32; i += 256) {
        int r = i >> 5, c4 = (i & 31) << 2;
        *(float4*)(sW + r * 136 + c4) = *(const float4*)(tfWoe + r * 128 + c4);
    }
    __syncthreads();

    // wV segment-sum (vectorized red) + fold-in tf32 conversion of score
    for (int idx = tid; idx < 64 * 32; idx += 256) {
        int r = idx >> 5, c4 = (idx & 31) << 2;
        float wgt = swv[r * 8 + (c4 >> 4)];
        float4 vv = *(const float4*)(g_Vh + sSrc[r] * 128 + c4);
        red4(&g_wV[sDst[r] * 128 + c4], vv.x * wgt, vv.y * wgt, vv.z * wgt, vv.w * wgt);
        float4 sc = *(float4*)(sS + r * 132 + c4);
        sc.x = f2tf_f(sc.x);
        sc.y = f2tf_f(sc.y);
        sc.z = f2tf_f(sc.z);
        sc.w = f2tf_f(sc.w);
        *(float4*)(sS + r * 132 + c4) = sc;
    }
    __syncthreads();

    // GEMM2: ee_pre = score @ Wo_e
    {
        float c2[2][4][4];
#pragma unroll
        for (int m = 0; m < 2; m++)
#pragma unroll
            for (int n = 0; n < 4; n++)
#pragma unroll
                for (int j = 0; j < 4; j++) c2[m][n][j] = 0.f;

#pragma unroll 2
        for (int k0 = 0; k0 < 128; k0 += 8) {
            uint32_t a[2][4];
#pragma unroll
            for (int m = 0; m < 2; m++) {
                int rr = wm * 32 + m * 16;
                a[m][0] = __float_as_uint(sS[(rr + g) * 132 + k0 + q]);
                a[m][1] = __float_as_uint(sS[(rr + g + 8) * 132 + k0 + q]);
                a[m][2] = __float_as_uint(sS[(rr + g) * 132 + k0 + q + 4]);
                a[m][3] = __float_as_uint(sS[(rr + g + 8) * 132 + k0 + q + 4]);
            }
#pragma unroll
            for (int n = 0; n < 4; n++) {
                uint32_t b0 = __float_as_uint(sW[(k0 + q) * 136 + nc0 + n * 8 + g]);
                uint32_t b1 = __float_as_uint(sW[(k0 + q + 4) * 136 + nc0 + n * 8 + g]);
                mma8(c2[0][n], a[0], b0, b1);
                mma8(c2[1][n], a[1], b0, b1);
            }
        }
#pragma unroll
        for (int m = 0; m < 2; m++)
#pragma unroll
            for (int n = 0; n < 4; n++) {
                int r0 = wm * 32 + m * 16 + g, r1 = r0 + 8;
                int cc = nc0 + n * 8 + 2 * q;
                sO[r0 * 132 + cc] = c2[m][n][0];
                sO[r0 * 132 + cc + 1] = c2[m][n][1];
                sO[r1 * 132 + cc] = c2[m][n][2];
                sO[r1 * 132 + cc + 1] = c2[m][n][3];
            }
    }
    __syncthreads();

    // epilogue: bias + residual (re-read e fp32) + store + stats
    const int tx = tid & 15, ty = tid >> 4;
    float4 bb0 = *(const float4*)(bo_e + tx * 8);
    float4 bb1 = *(const float4*)(bo_e + tx * 8 + 4);
    float bias[8] = {bb0.x, bb0.y, bb0.z, bb0.w, bb1.x, bb1.y, bb1.z, bb1.w};
    float csum[8] = {0, 0, 0, 0, 0, 0, 0, 0};
    float csq[8] = {0, 0, 0, 0, 0, 0, 0, 0};
#pragma unroll
    for (int i = 0; i < 4; i++) {
        int r = ty * 4 + i;
        float4 e0 = *(const float4*)(e + (row0 + r) * D + tx * 8);
        float4 e1 = *(const float4*)(e + (row0 + r) * D + tx * 8 + 4);
        float ev[8] = {e0.x, e0.y, e0.z, e0.w, e1.x, e1.y, e1.z, e1.w};
        float o[8];
#pragma unroll
        for (int j = 0; j < 8; j++) {
            o[j] = sO[r * 132 + tx * 8 + j] + bias[j] + ev[j];
            csum[j] += o[j];
            csq[j] += o[j] * o[j];
        }
        *(float4*)(g_ee + (row0 + r) * 128 + tx * 8) = make_float4(o[0], o[1], o[2], o[3]);
        *(float4*)(g_ee + (row0 + r) * 128 + tx * 8 + 4) = make_float4(o[4], o[5], o[6], o[7]);
    }
#pragma unroll
    for (int j = 0; j < 8; j++) {
        atomicAdd(&sCS[tx * 8 + j], csum[j]);
        atomicAdd(&sCQ[tx * 8 + j], csq[j]);
    }
    __syncthreads();
    if (tid < 128) {
        atomicAdd(&g_stats[0 * 128 + tid], sCS[tid]);
        atomicAdd(&g_stats[1 * 128 + tid], sCQ[tid]);
    }
}

// ---------------- node attention output (tf32 mma) ----------------
__global__ __launch_bounds__(256, 1) void k_nattn(const float* __restrict__ h,
                                                  const float* __restrict__ bo_h) {
    extern __shared__ float sm[];
    float* sA = sm;                 // 128 x 132 (tf32 h_attn)
    float* sB = sA + 128 * 132;     // 128 x 136 (tf32 Wo_h)
    float* sO = sB + 128 * 136;     // 128 x 132
    float* sCS = sO + 128 * 132;    // 128
    float* sCQ = sCS + 128;         // 128
    const int tid = threadIdx.x;
    const int lane = tid & 31, wid = tid >> 5;
    const int g = lane >> 2, q = lane & 3;
    const int wm = wid >> 1, wn = wid & 1;
    const int tx = tid & 15, ty = tid >> 4;
    const int row0 = blockIdx.x * 128;

    for (int i = tid; i < 128 * 128; i += 256) {
        int r = i >> 7, c = i & 127;
        int gr = row0 + r;
        float v = 0.f;
        if (gr < NN) {
            float zz = g_z[gr * 8 + (c >> 4)];
            v = g_wV[gr * 128 + c] / (zz + 1e-6f);
        }
        sA[r * 132 + c] = f2tf_f(v);
    }
    for (int i = tid; i < 128 * 32; i += 256) {
        int r = i >> 5, c4 = (i & 31) << 2;
        *(float4*)(sB + r * 136 + c4) = *(const float4*)(g_tfw + TOH + r * 128 + c4);
    }
    if (tid < 128) { sCS[tid] = 0.f; sCQ[tid] = 0.f; }
    __syncthreads();

    float acc[2][8][4];
#pragma unroll
    for (int m = 0; m < 2; m++)
#pragma unroll
        for (int n = 0; n < 8; n++)
#pragma unroll
            for (int j = 0; j < 4; j++) acc[m][n][j] = 0.f;

#pragma unroll 2
    for (int k0 = 0; k0 < 128; k0 += 8) {
        uint32_t a[2][4];
#pragma unroll
        for (int m = 0; m < 2; m++) {
            int rr = wm * 32 + m * 16;
            a[m][0] = __float_as_uint(sA[(rr + g) * 132 + k0 + q]);
            a[m][1] = __float_as_uint(sA[(rr + g + 8) * 132 + k0 + q]);
            a[m][2] = __float_as_uint(sA[(rr + g) * 132 + k0 + q + 4]);
            a[m][3] = __float_as_uint(sA[(rr + g + 8) * 132 + k0 + q + 4]);
        }
#pragma unroll
        for (int n = 0; n < 8; n++) {
            uint32_t b0 = __float_as_uint(sB[(k0 + q) * 136 + wn * 64 + n * 8 + g]);
            uint32_t b1 = __float_as_uint(sB[(k0 + q + 4) * 136 + wn * 64 + n * 8 + g]);
            mma8(acc[0][n], a[0], b0, b1);
            mma8(acc[1][n], a[1], b0, b1);
        }
    }
#pragma unroll
    for (int m = 0; m < 2; m++)
#pragma unroll
        for (int n = 0; n < 8; n++) {
            int r0 = wm * 32 + m * 16 + g, r1 = r0 + 8;
            int cc = wn * 64 + n * 8 + 2 * q;
            sO[r0 * 132 + cc] = acc[m][n][0];
            sO[r0 * 132 + cc + 1] = acc[m][n][1];
            sO[r1 * 132 + cc] = acc[m][n][2];
            sO[r1 * 132 + cc + 1] = acc[m][n][3];
        }
    __syncthreads();

    float4 bb0 = *(const float4*)(bo_h + tx * 8);
    float4 bb1 = *(const float4*)(bo_h + tx * 8 + 4);
    float bias[8] = {bb0.x, bb0.y, bb0.z, bb0.w, bb1.x, bb1.y, bb1.z, bb1.w};
    float csum[8] = {0, 0, 0, 0, 0, 0, 0, 0};
    float csq[8] = {0, 0, 0, 0, 0, 0, 0, 0};
#pragma unroll
    for (int i = 0; i < 8; i++) {
        int r = ty * 8 + i;
        int gr = row0 + r;
        if (gr < NN) {
            float4 r0 = *(const float4*)(h + gr * 128 + tx * 8);
            float4 r1 = *(const float4*)(h + gr * 128 + tx * 8 + 4);
            float hv[8] = {r0.x, r0.y, r0.z, r0.w, r1.x, r1.y, r1.z, r1.w};
            float o[8];
#pragma unroll
            for (int j = 0; j < 8; j++) {
                o[j] = sO[r * 132 + tx * 8 + j] + bias[j] + hv[j];
                csum[j] += o[j];
                csq[j] += o[j] * o[j];
            }
            *(float4*)(g_hh + gr * 128 + tx * 8) = make_float4(o[0], o[1], o[2], o[3]);
            *(float4*)(g_hh + gr * 128 + tx * 8 + 4) = make_float4(o[4], o[5], o[6], o[7]);
        }
    }
#pragma unroll
    for (int j = 0; j < 8; j++) {
        atomicAdd(&sCS[tx * 8 + j], csum[j]);
        atomicAdd(&sCQ[tx * 8 + j], csq[j]);
    }
    __syncthreads();
    if (tid < 128) {
        atomicAdd(&g_stats[2 * 128 + tid], sCS[tid]);
        atomicAdd(&g_stats[3 * 128 + tid], sCQ[tid]);
    }
}

// ---------------- finalize BN stats ----------------
__global__ void k_finalize(int statOff, float cnt, int bnOff) {
    int c = threadIdx.x;  // 128
    float m = g_stats[statOff + c] / cnt;
    float var = g_stats[statOff + 128 + c] / cnt - m * m;
    g_bnp[bnOff + c] = m;
    g_bnp[bnOff + 128 + c] = rsqrtf(var + 1e-5f);
}

// ---------------- k_ffn prefetch helper ----------------
__device__ __forceinline__ void ffn_prefetch(const float* W1t, const float* W2t,
                                             float* sW1buf, float* sW2buf, int ch, int tid) {
    uint32_t d1 = (uint32_t)__cvta_generic_to_shared(sW1buf);
#pragma unroll
    for (int j = 0; j < 4; j++) {
        int idx = tid + j * 256;
        int r = idx >> 3, c4 = (idx & 7) << 2;
        cpasync16(d1 + (uint32_t)(r * 40 + c4) * 4u, W1t + r * 256 + ch * 32 + c4);
    }
    uint32_t d2 = (uint32_t)__cvta_generic_to_shared(sW2buf);
#pragma unroll
    for (int j = 0; j < 4; j++) {
        int idx = tid + j * 256;
        int r = idx >> 5, c4 = (idx & 31) << 2;
        cpasync16(d2 + (uint32_t)(r * 136 + c4) * 4u, W2t + (ch * 32 + r) * 128 + c4);
    }
    asm volatile("cp.async.commit_group;" ::: "memory");
}

// ---------------- fused BN1 + FFN + residual + stats2 (tf32, cp.async double-buffered) ----------------
__global__ __launch_bounds__(256, 1) void k_ffn(const float* __restrict__ xin, float* xout,
                                                int bnOff,
                                                const float* __restrict__ gam,
                                                const float* __restrict__ bet,
                                                const float* __restrict__ W1t,   // tf32 128x256
                                                const float* __restrict__ ba,
                                                const float* __restrict__ W2t,   // tf32 256x128
                                                const float* __restrict__ bb2,
                                                int statOff, int nrows) {
    extern __shared__ float sm[];
    float* sX = sm;                      // 128x132 tf32 post-BN
    float* sW1 = sX + 128 * 132;         // 2 x 128x40
    float* sY = sW1 + 2 * 128 * 40;      // 128x36
    float* sW2 = sY + 128 * 36;          // 2 x 32x136
    float* sCS = sW2 + 2 * 32 * 136;     // 128
    float* sCQ = sCS + 128;              // 128
    float* sO = sW1;                     // overlay 128x132 (epilogue only)

    const int tid = threadIdx.x;
    const int lane = tid & 31, wid = tid >> 5;
    const int g = lane >> 2, q = lane & 3;
    const int wm = wid >> 1, wn = wid & 1;
    const int row0 = blockIdx.x * 128;
    const float* mean = g_bnp + bnOff;
    const float* istd = g_bnp + bnOff + 128;

    for (int i = tid; i < 128 * 128; i += 256) {
        int r = i >> 7, c = i & 127;
        int gr = row0 + r;
        float v = 0.f;
        if (gr < nrows) v = (xin[(size_t)gr * 128 + c] - mean[c]) * istd[c] * gam[c] + bet[c];
        sX[r * 132 + c] = f2tf_f(v);
    }
    if (tid < 128) { sCS[tid] = 0.f; sCQ[tid] = 0.f; }

    ffn_prefetch(W1t, W2t, sW1, sW2, 0, tid);
    ffn_prefetch(W1t, W2t, sW1 + 128 * 40, sW2 + 32 * 136, 1, tid);

    float accO[2][8][4];
#pragma unroll
    for (int m = 0; m < 2; m++)
#pragma unroll
        for (int n = 0; n < 8; n++)
#pragma unroll
            for (int j = 0; j < 4; j++) accO[m][n][j] = 0.f;

    for (int ch = 0; ch < 8; ch++) {
        int buf = ch & 1;
        if (ch < 7) { asm volatile("cp.async.wait_group 1;" ::: "memory"); }
        else        { asm volatile("cp.async.wait_group 0;" ::: "memory"); }
        __syncthreads();
        const float* w1 = sW1 + buf * 128 * 40;
        const float* w2 = sW2 + buf * 32 * 136;

        // GEMM1: y = relu(sX @ W1chunk + b1chunk)   out 128 x 32
        float c1[2][2][4];
#pragma unroll
        for (int m = 0; m < 2; m++)
#pragma unroll
            for (int n = 0; n < 2; n++)
#pragma unroll
                for (int j = 0; j < 4; j++) c1[m][n][j] = 0.f;

        const int cn = wn * 16;
#pragma unroll 2
        for (int k0 = 0; k0 < 128; k0 += 8) {
            uint32_t a[2][4];
#pragma unroll
            for (int m = 0; m < 2; m++) {
                int rr = wm * 32 + m * 16;
                a[m][0] = __float_as_uint(sX[(rr + g) * 132 + k0 + q]);
                a[m][1] = __float_as_uint(sX[(rr + g + 8) * 132 + k0 + q]);
                a[m][2] = __float_as_uint(sX[(rr + g) * 132 + k0 + q + 4]);
                a[m][3] = __float_as_uint(sX[(rr + g + 8) * 132 + k0 + q + 4]);
            }
#pragma unroll
            for (int n = 0; n < 2; n++) {
                uint32_t b0 = __float_as_uint(w1[(k0 + q) * 40 + cn + n * 8 + g]);
                uint32_t b1 = __float_as_uint(w1[(k0 + q + 4) * 40 + cn + n * 8 + g]);
                mma8(c1[0][n], a[0], b0, b1);
                mma8(c1[1][n], a[1], b0, b1);
            }
        }
#pragma unroll
        for (int m = 0; m < 2; m++)
#pragma unroll
            for (int n = 0; n < 2; n++) {
                int cc = cn + n * 8 + 2 * q;
                float bv0 = ba[ch * 32 + cc], bv1 = ba[ch * 32 + cc + 1];
                int r0 = wm * 32 + m * 16 + g, r1 = r0 + 8;
                sY[r0 * 36 + cc] = f2tf_f(fmaxf(c1[m][n][0] + bv0, 0.f));
                sY[r0 * 36 + cc + 1] = f2tf_f(fmaxf(c1[m][n][1] + bv1, 0.f));
                sY[r1 * 36 + cc] = f2tf_f(fmaxf(c1[m][n][2] + bv0, 0.f));
                sY[r1 * 36 + cc + 1] = f2tf_f(fmaxf(c1[m][n][3] + bv1, 0.f));
            }
        __syncthreads();

        // GEMM2 accumulate: out += y @ W2chunk   (k = 32)
#pragma unroll
        for (int k0 = 0; k0 < 32; k0 += 8) {
            uint32_t a[2][4];
#pragma unroll
            for (int m = 0; m < 2; m++) {
                int rr = wm * 32 + m * 16;
                a[m][0] = __float_as_uint(sY[(rr + g) * 36 + k0 + q]);
                a[m][1] = __float_as_uint(sY[(rr + g + 8) * 36 + k0 + q]);
                a[m][2] = __float_as_uint(sY[(rr + g) * 36 + k0 + q + 4]);
                a[m][3] = __float_as_uint(sY[(rr + g + 8) * 36 + k0 + q + 4]);
            }
#pragma unroll
            for (int n = 0; n < 8; n++) {
                uint32_t b0 = __float_as_uint(w2[(k0 + q) * 136 + wn * 64 + n * 8 + g]);
                uint32_t b1 = __float_as_uint(w2[(k0 + q + 4) * 136 + wn * 64 + n * 8 + g]);
                mma8(accO[0][n], a[0], b0, b1);
                mma8(accO[1][n], a[1], b0, b1);
            }
        }
        __syncthreads();
        if (ch + 2 < 8)
            ffn_prefetch(W1t, W2t, sW1 + buf * 128 * 40, sW2 + buf * 32 * 136, ch + 2, tid);
    }

    // stage output frags to sO (overlay; all cp.async retired, all reads done)
#pragma unroll
    for (int m = 0; m < 2; m++)
#pragma unroll
        for (int n = 0; n < 8; n++) {
            int r0 = wm * 32 + m * 16 + g, r1 = r0 + 8;
            int cc = wn * 64 + n * 8 + 2 * q;
            sO[r0 * 132 + cc] = accO[m][n][0];
            sO[r0 * 132 + cc + 1] = accO[m][n][1];
            sO[r1 * 132 + cc] = accO[m][n][2];
            sO[r1 * 132 + cc + 1] = accO[m][n][3];
        }
    __syncthreads();

    // epilogue: bias + residual (recompute BN fp32 from re-read xin) + store + stats
    const int tx = tid & 15, ty = tid >> 4;
    float4 c0 = *(const float4*)(bb2 + tx * 8);
    float4 c1v = *(const float4*)(bb2 + tx * 8 + 4);
    float bias[8] = {c0.x, c0.y, c0.z, c0.w, c1v.x, c1v.y, c1v.z, c1v.w};
    float mn[8], is_[8], gm[8], bt[8];
#pragma unroll
    for (int j = 0; j < 8; j++) {
        int c = tx * 8 + j;
        mn[j] = mean[c]; is_[j] = istd[c]; gm[j] = gam[c]; bt[j] = bet[c];
    }
    float csum[8] = {0, 0, 0, 0, 0, 0, 0, 0};
    float csq[8] = {0, 0, 0, 0, 0, 0, 0, 0};
#pragma unroll
    for (int i = 0; i < 8; i++) {
        int r = ty * 8 + i;
        int gr = row0 + r;
        if (gr < nrows) {
            float4 x0 = *(const float4*)(xin + (size_t)gr * 128 + tx * 8);
            float4 x1 = *(const float4*)(xin + (size_t)gr * 128 + tx * 8 + 4);
            float xv[8] = {x0.x, x0.y, x0.z, x0.w, x1.x, x1.y, x1.z, x1.w};
            float o[8];
#pragma unroll
            for (int j = 0; j < 8; j++) {
                float resid = (xv[j] - mn[j]) * is_[j] * gm[j] + bt[j];
                o[j] = sO[r * 132 + tx * 8 + j] + bias[j] + resid;
                csum[j] += o[j];
                csq[j] += o[j] * o[j];
            }
            *(float4*)(xout + (size_t)gr * 128 + tx * 8) = make_float4(o[0], o[1], o[2], o[3]);
            *(float4*)(xout + (size_t)gr * 128 + tx * 8 + 4) = make_float4(o[4], o[5], o[6], o[7]);
        }
    }
#pragma unroll
    for (int j = 0; j < 8; j++) {
        atomicAdd(&sCS[tx * 8 + j], csum[j]);
        atomicAdd(&sCQ[tx * 8 + j], csq[j]);
    }
    __syncthreads();
    if (tid < 128) {
        atomicAdd(&g_stats[statOff + tid], sCS[tid]);
        atomicAdd(&g_stats[statOff + 128 + tid], sCQ[tid]);
    }
}

// ---------------- final BN (elementwise) ----------------
__global__ void k_bnout(const float* x, int bnOff, const float* gam, const float* bet,
                        float* o, int nrows) {
    const float* mean = g_bnp + bnOff;
    const float* istd = g_bnp + bnOff + 128;
    int idx = blockIdx.x * blockDim.x + threadIdx.x;
    int stride = gridDim.x * blockDim.x;
    int total = nrows * 32;  // float4 units
    for (int i = idx; i < total; i += stride) {
        int c = (i & 31) << 2;
        float4 v = *(const float4*)(x + (size_t)i * 4);
        float4 r;
        r.x = (v.x - mean[c + 0]) * istd[c + 0] * gam[c + 0] + bet[c + 0];
        r.y = (v.y - mean[c + 1]) * istd[c + 1] * gam[c + 1] + bet[c + 1];
        r.z = (v.z - mean[c + 2]) * istd[c + 2] * gam[c + 2] + bet[c + 2];
        r.w = (v.w - mean[c + 3]) * istd[c + 3] * gam[c + 3] + bet[c + 3];
        *(float4*)(o + (size_t)i * 4) = r;
    }
}

// ---------------- launch ----------------
extern "C" void kernel_launch(void* const* d_in, const int* in_sizes, int n_in,
                              void* d_out, int out_size) {
    const float* h = (const float*)d_in[0];
    const float* e = (const float*)d_in[1];
    const int* src = (const int*)d_in[2];
    const int* dst = (const int*)d_in[3];
    const float* Wq = (const float*)d_in[4];
    const float* Wk = (const float*)d_in[5];
    const float* Wv = (const float*)d_in[6];
    const float* We = (const float*)d_in[7];
    const float* Wo_h = (const float*)d_in[8];
    const float* bo_h = (const float*)d_in[9];
    const float* Wo_e = (const float*)d_in[10];
    const float* bo_e = (const float*)d_in[11];
    const float* g1h = (const float*)d_in[12];
    const float* b1h = (const float*)d_in[13];
    const float* g1e = (const float*)d_in[14];
    const float* b1e = (const float*)d_in[15];
    const float* Wf1h = (const float*)d_in[16];
    const float* bf1h = (const float*)d_in[17];
    const float* Wf2h = (const float*)d_in[18];
    const float* bf2h = (const float*)d_in[19];
    const float* Wf1e = (const float*)d_in[20];
    const float* bf1e = (const float*)d_in[21];
    const float* Wf2e = (const float*)d_in[22];
    const float* bf2e = (const float*)d_in[23];
    const float* g2h = (const float*)d_in[24];
    const float* b2h = (const float*)d_in[25];
    const float* g2e = (const float*)d_in[26];
    const float* b2e = (const float*)d_in[27];
    float* out = (float*)d_out;
    float* out_e = out + (size_t)NN * D;

    float *p_hh, *p_h2, *p_ee, *p_tfw;
    cudaGetSymbolAddress((void**)&p_hh, g_hh);
    cudaGetSymbolAddress((void**)&p_h2, g_h2);
    cudaGetSymbolAddress((void**)&p_ee, g_ee);
    cudaGetSymbolAddress((void**)&p_tfw, g_tfw);

    const int smQ = (128 * 132 + 128 * 136 + 128 * 132) * 4;
    const int smN = smQ + 256 * 4;
    const int sm1 = (64 * 132 * 3 + 128 * 136 + 512 + 256 + 128) * 4;
    const int smF = (128 * 132 + 2 * 128 * 40 + 128 * 36 + 2 * 32 * 136 + 256) * 4;
    cudaFuncSetAttribute(k_qkv, cudaFuncAttributeMaxDynamicSharedMemorySize, smQ);
    cudaFuncSetAttribute(k_nattn, cudaFuncAttributeMaxDynamicSharedMemorySize, smN);
    cudaFuncSetAttribute(k_edge1, cudaFuncAttributeMaxDynamicSharedMemorySize, sm1);
    cudaFuncSetAttribute(k_ffn, cudaFuncAttributeMaxDynamicSharedMemorySize, smF);

    const int NBLK = (NN + 127) / 128;  // 391

    k_zero<<<2048, 256>>>();
    k_prep<<<256, 256>>>(Wq, Wk, Wv, We, Wo_h, Wo_e, Wf1h, Wf2h, Wf1e, Wf2e);
    k_qkv<<<NBLK, 256, smQ>>>(h);
    k_edge1<<<NE / 64, 256, sm1>>>(e, src, dst, bo_e);
    k_nattn<<<NBLK, 256, smN>>>(h, bo_h);
    k_finalize<<<1, 128>>>(0, (float)NE, 0);      // bn1e
    k_finalize<<<1, 128>>>(256, (float)NN, 256);  // bn1h
    k_ffn<<<NE / 128, 256, smF>>>(p_ee, out_e, 0, g1e, b1e, p_tfw + T1E, bf1e, p_tfw + T2E, bf2e, 512, NE);
    k_ffn<<<NBLK, 256, smF>>>(p_hh, p_h2, 256, g1h, b1h, p_tfw + T1H, bf1h, p_tfw + T2H, bf2h, 768, NN);
    k_finalize<<<1, 128>>>(512, (float)NE, 512);  // bn2e
    k_finalize<<<1, 128>>>(768, (float)NN, 768);  // bn2h
    k_bnout<<<2960, 256>>>(p_h2, 768, g2h, b2h, out, NN);
    k_bnout<<<2960, 256>>>(out_e, 512, g2e, b2e, out_e, NE);
}

// round 10
// speedup vs baseline: 2.2021x; 1.2898x over previous
#include <cuda_runtime.h>
#include <math.h>
#include <stdint.h>

#define NN 50000
#define NE 640000
#define D 128

// ---------------- scratch (device globals; no cudaMalloc allowed) ----------------
__device__ float g_Qh[NN * D];
__device__ float g_Kh[NN * D];
__device__ float g_Vh[NN * D];
__device__ float g_wV[NN * D];
__device__ float g_z[NN * 8];
__device__ float g_hh[NN * D];
__device__ float g_h2[NN * D];
__device__ float g_ee[NE * D];
__device__ float g_stats[8 * 128];
__device__ float g_bnp[8 * 128];
__device__ float g_tfw[229376];   // tf32 pre-converted weights

// offsets inside g_tfw
#define TQ  0
#define TK  16384
#define TV  32768
#define TE  49152
#define TOH 65536
#define TOE 81920
#define T1H 98304
#define T2H 131072
#define T1E 163840
#define T2E 196608

// ---------------- tf32 mma helpers ----------------
__device__ __forceinline__ uint32_t f2tf(float x) {
    uint32_t r;
    asm("cvt.rna.tf32.f32 %0, %1;" : "=r"(r) : "f"(x));
    return r;
}
__device__ __forceinline__ float f2tf_f(float x) { return __uint_as_float(f2tf(x)); }

__device__ __forceinline__ void mma8(float c[4], const uint32_t a[4], uint32_t b0, uint32_t b1) {
    asm volatile(
        "mma.sync.aligned.m16n8k8.row.col.f32.tf32.tf32.f32 "
        "{%0,%1,%2,%3}, {%4,%5,%6,%7}, {%8,%9}, {%0,%1,%2,%3};"
        : "+f"(c[0]), "+f"(c[1]), "+f"(c[2]), "+f"(c[3])
        : "r"(a[0]), "r"(a[1]), "r"(a[2]), "r"(a[3]), "r"(b0), "r"(b1));
}

__device__ __forceinline__ void red4(float* p, float x, float y, float z, float w) {
    asm volatile("red.global.add.v4.f32 [%0], {%1,%2,%3,%4};"
                 :: "l"(p), "f"(x), "f"(y), "f"(z), "f"(w) : "memory");
}

__device__ __forceinline__ void cpasync16(uint32_t s, const void* g) {
    asm volatile("cp.async.cg.shared.global [%0], [%1], 16;" :: "r"(s), "l"(g));
}

// ---------------- weight pre-conversion (tf32-rna, once per call) ----------------
__global__ void k_prep(const float* Wq, const float* Wk, const float* Wv, const float* We,
                       const float* Woh, const float* Woe, const float* W1h, const float* W2h,
                       const float* W1e, const float* W2e) {
    int i = blockIdx.x * blockDim.x + threadIdx.x;
    int stride = gridDim.x * blockDim.x;
    for (; i < 229376; i += stride) {
        float v;
        if (i < 16384) v = Wq[i];
        else if (i < 32768) v = Wk[i - 16384];
        else if (i < 49152) v = Wv[i - 32768];
        else if (i < 65536) v = We[i - 49152];
        else if (i < 81920) v = Woh[i - 65536];
        else if (i < 98304) v = Woe[i - 81920];
        else if (i < 131072) v = W1h[i - 98304];
        else if (i < 163840) v = W2h[i - 131072];
        else if (i < 196608) v = W1e[i - 163840];
        else v = W2e[i - 196608];
        g_tfw[i] = f2tf_f(v);
    }
}

// ---------------- zero accumulators ----------------
__global__ void k_zero() {
    int idx = blockIdx.x * blockDim.x + threadIdx.x;
    int stride = gridDim.x * blockDim.x;
    const int nwv = NN * D, nz = NN * 8, nst = 8 * 128;
    for (int i = idx; i < nwv; i += stride) g_wV[i] = 0.f;
    for (int i = idx; i < nz; i += stride) g_z[i] = 0.f;
    for (int i = idx; i < nst; i += stride) g_stats[i] = 0.f;
}

// ---------------- Q/K/V GEMMs (tf32 mma, 2 CTAs/SM, fragment-direct stores) ----------------
__global__ __launch_bounds__(256, 2) void k_qkv(const float* __restrict__ h) {
    extern __shared__ float sm[];
    float* sA = sm;                 // 128 x 132 (tf32 of h)
    float* sB = sA + 128 * 132;     // 64 x 136 (tf32 weight k-chunk)
    const int tid = threadIdx.x;
    const int lane = tid & 31, wid = tid >> 5;
    const int g = lane >> 2, q = lane & 3;
    const int wm = wid >> 1, wn = wid & 1;
    const int row0 = blockIdx.x * 128;

    for (int i = tid; i < 128 * 32; i += 256) {
        int r = i >> 5, c4 = (i & 31) << 2;
        float4 v = make_float4(0.f, 0.f, 0.f, 0.f);
        if (row0 + r < NN) v = *(const float4*)(h + (row0 + r) * D + c4);
        sA[r * 132 + c4 + 0] = f2tf_f(v.x);
        sA[r * 132 + c4 + 1] = f2tf_f(v.y);
        sA[r * 132 + c4 + 2] = f2tf_f(v.z);
        sA[r * 132 + c4 + 3] = f2tf_f(v.w);
    }

    for (int wsel = 0; wsel < 3; wsel++) {
        const float* W = g_tfw + wsel * 16384;   // TQ, TK, TV
        float* outp = (wsel == 0) ? g_Qh : (wsel == 1) ? g_Kh : g_Vh;

        float acc[2][8][4];
#pragma unroll
        for (int m = 0; m < 2; m++)
#pragma unroll
            for (int n = 0; n < 8; n++)
#pragma unroll
                for (int j = 0; j < 4; j++) acc[m][n][j] = 0.f;

        for (int half = 0; half < 2; half++) {
            __syncthreads();   // previous consumers of sB done
            for (int i = tid; i < 64 * 32; i += 256) {
                int r = i >> 5, c4 = (i & 31) << 2;
                *(float4*)(sB + r * 136 + c4) = *(const float4*)(W + (half * 64 + r) * 128 + c4);
            }
            __syncthreads();

#pragma unroll 2
            for (int k0 = 0; k0 < 64; k0 += 8) {
                int kk = half * 64 + k0;
                uint32_t a[2][4];
#pragma unroll
                for (int m = 0; m < 2; m++) {
                    int rr = wm * 32 + m * 16;
                    a[m][0] = __float_as_uint(sA[(rr + g) * 132 + kk + q]);
                    a[m][1] = __float_as_uint(sA[(rr + g + 8) * 132 + kk + q]);
                    a[m][2] = __float_as_uint(sA[(rr + g) * 132 + kk + q + 4]);
                    a[m][3] = __float_as_uint(sA[(rr + g + 8) * 132 + kk + q + 4]);
                }
#pragma unroll
                for (int n = 0; n < 8; n++) {
                    uint32_t b0 = __float_as_uint(sB[(k0 + q) * 136 + wn * 64 + n * 8 + g]);
                    uint32_t b1 = __float_as_uint(sB[(k0 + q + 4) * 136 + wn * 64 + n * 8 + g]);
                    mma8(acc[0][n], a[0], b0, b1);
                    mma8(acc[1][n], a[1], b0, b1);
                }
            }
        }

        // fragment-direct stores (4-lane groups write contiguous 32B => sector-efficient)
#pragma unroll
        for (int m = 0; m < 2; m++)
#pragma unroll
            for (int n = 0; n < 8; n++) {
                int r0 = wm * 32 + m * 16 + g, r1 = r0 + 8;
                int cc = wn * 64 + n * 8 + 2 * q;
                if (row0 + r0 < NN)
                    *(float2*)(outp + (size_t)(row0 + r0) * 128 + cc) =
                        make_float2(acc[m][n][0], acc[m][n][1]);
                if (row0 + r1 < NN)
                    *(float2*)(outp + (size_t)(row0 + r1) * 128 + cc) =
                        make_float2(acc[m][n][2], acc[m][n][3]);
            }
    }
}

// ---------------- fused edge kernel (tf32 mma, 2 CTAs/SM via k-split weights) ----------------
__global__ __launch_bounds__(256, 2) void k_edge1(const float* __restrict__ e,
                                                  const int* __restrict__ src,
                                                  const int* __restrict__ dst,
                                                  const float* __restrict__ bo_e) {
    extern __shared__ float sm[];
    float* sE = sm;                    // 64 x 132 (e tile tf32); aliased by sO after GEMM1
    float* sS = sE + 64 * 132;         // 64 x 132 (P fp32 -> score fp32 -> tf32)
    float* sW = sS + 64 * 132;         // 64 x 136 (tf32 weight k-chunk)
    float* swv = sW + 64 * 136;        // 64 x 8
    float* sCS = swv + 512;            // 128
    float* sCQ = sCS + 128;            // 128
    int* sSrc = (int*)(sCQ + 128);     // 64
    int* sDst = sSrc + 64;             // 64
    float* sO = sE;                    // overlay (sE dead after GEMM1)

    const float* tfWe = g_tfw + TE;
    const float* tfWoe = g_tfw + TOE;

    const int tid = threadIdx.x;
    const int lane = tid & 31, wid = tid >> 5;
    const int g = lane >> 2, q = lane & 3;
    const int wm = wid >> 2, wn = wid & 3;   // warp tile: 32 rows x 32 cols
    const int nc0 = wn * 32;
    const int row0 = blockIdx.x * 64;

    for (int i = tid; i < 64 * 32; i += 256) {
        int r = i >> 5, c4 = (i & 31) << 2;
        float4 v = *(const float4*)(e + (row0 + r) * D + c4);
        sE[r * 132 + c4 + 0] = f2tf_f(v.x);
        sE[r * 132 + c4 + 1] = f2tf_f(v.y);
        sE[r * 132 + c4 + 2] = f2tf_f(v.z);
        sE[r * 132 + c4 + 3] = f2tf_f(v.w);
    }
    for (int i = tid; i < 64 * 32; i += 256) {
        int r = i >> 5, c4 = (i & 31) << 2;
        *(float4*)(sW + r * 136 + c4) = *(const float4*)(tfWe + r * 128 + c4);
    }
    if (tid < 64) { sSrc[tid] = src[row0 + tid]; sDst[tid] = dst[row0 + tid]; }
    if (tid < 128) { sCS[tid] = 0.f; sCQ[tid] = 0.f; }
    __syncthreads();

    // GEMM1: P = e @ We (k-split halves, accumulators persist)
    {
        float c1[2][4][4];
#pragma unroll
        for (int m = 0; m < 2; m++)
#pragma unroll
            for (int n = 0; n < 4; n++)
#pragma unroll
                for (int j = 0; j < 4; j++) c1[m][n][j] = 0.f;

        for (int half = 0; half < 2; half++) {
            if (half) {
                __syncthreads();
                for (int i = tid; i < 64 * 32; i += 256) {
                    int r = i >> 5, c4 = (i & 31) << 2;
                    *(float4*)(sW + r * 136 + c4) = *(const float4*)(tfWe + (64 + r) * 128 + c4);
                }
                __syncthreads();
            }
#pragma unroll 2
            for (int k0 = 0; k0 < 64; k0 += 8) {
                int kk = half * 64 + k0;
                uint32_t a[2][4];
#pragma unroll
                for (int m = 0; m < 2; m++) {
                    int rr = wm * 32 + m * 16;
                    a[m][0] = __float_as_uint(sE[(rr + g) * 132 + kk + q]);
                    a[m][1] = __float_as_uint(sE[(rr + g + 8) * 132 + kk + q]);
                    a[m][2] = __float_as_uint(sE[(rr + g) * 132 + kk + q + 4]);
                    a[m][3] = __float_as_uint(sE[(rr + g + 8) * 132 + kk + q + 4]);
                }
#pragma unroll
                for (int n = 0; n < 4; n++) {
                    uint32_t b0 = __float_as_uint(sW[(k0 + q) * 136 + nc0 + n * 8 + g]);
                    uint32_t b1 = __float_as_uint(sW[(k0 + q + 4) * 136 + nc0 + n * 8 + g]);
                    mma8(c1[0][n], a[0], b0, b1);
                    mma8(c1[1][n], a[1], b0, b1);
                }
            }
        }
#pragma unroll
        for (int m = 0; m < 2; m++)
#pragma unroll
            for (int n = 0; n < 4; n++) {
                int r0 = wm * 32 + m * 16 + g, r1 = r0 + 8;
                int cc = nc0 + n * 8 + 2 * q;
                sS[r0 * 132 + cc] = c1[m][n][0];
                sS[r0 * 132 + cc + 1] = c1[m][n][1];
                sS[r1 * 132 + cc] = c1[m][n][2];
                sS[r1 * 132 + cc + 1] = c1[m][n][3];
            }
    }
    __syncthreads();

    // score = P * Kh[src] * Qh[dst] / 4  (in place, fp32)
    for (int i = tid; i < 64 * 32; i += 256) {
        int r = i >> 5, c4 = (i & 31) << 2;
        int s = sSrc[r], d = sDst[r];
        float4 p = *(float4*)(sS + r * 132 + c4);
        float4 kv = *(const float4*)(g_Kh + s * 128 + c4);
        float4 qv = *(const float4*)(g_Qh + d * 128 + c4);
        p.x *= kv.x * qv.x * 0.25f;
        p.y *= kv.y * qv.y * 0.25f;
        p.z *= kv.z * qv.z * 0.25f;
        p.w *= kv.w * qv.w * 0.25f;
        *(float4*)(sS + r * 132 + c4) = p;
    }
    __syncthreads();

    // per-head weights + z segment-sum (fp32); refill sW with Wo_e lo
    for (int idx = tid; idx < 64 * 8; idx += 256) {
        int r = idx >> 3, hd = idx & 7;
        float ssum = 0.f;
#pragma unroll
        for (int t = 0; t < 16; t++) ssum += sS[r * 132 + hd * 16 + t];
        ssum = fminf(fmaxf(ssum, -5.f), 5.f);
        float wv = __expf(ssum);
        swv[idx] = wv;
        atomicAdd(&g_z[sDst[r] * 8 + hd], wv);
    }
    for (int i = tid; i < 64 * 32; i += 256) {
        int r = i >> 5, c4 = (i & 31) << 2;
        *(float4*)(sW + r * 136 + c4) = *(const float4*)(tfWoe + r * 128 + c4);
    }
    __syncthreads();

    // wV segment-sum (vectorized red) + fold-in tf32 conversion of score
    for (int idx = tid; idx < 64 * 32; idx += 256) {
        int r = idx >> 5, c4 = (idx & 31) << 2;
        float wgt = swv[r * 8 + (c4 >> 4)];
        float4 vv = *(const float4*)(g_Vh + sSrc[r] * 128 + c4);
        red4(&g_wV[sDst[r] * 128 + c4], vv.x * wgt, vv.y * wgt, vv.z * wgt, vv.w * wgt);
        float4 sc = *(float4*)(sS + r * 132 + c4);
        sc.x = f2tf_f(sc.x);
        sc.y = f2tf_f(sc.y);
        sc.z = f2tf_f(sc.z);
        sc.w = f2tf_f(sc.w);
        *(float4*)(sS + r * 132 + c4) = sc;
    }
    __syncthreads();

    // GEMM2: ee_pre = score @ Wo_e (k-split halves)
    {
        float c2[2][4][4];
#pragma unroll
        for (int m = 0; m < 2; m++)
#pragma unroll
            for (int n = 0; n < 4; n++)
#pragma unroll
                for (int j = 0; j < 4; j++) c2[m][n][j] = 0.f;

        for (int half = 0; half < 2; half++) {
            if (half) {
                __syncthreads();
                for (int i = tid; i < 64 * 32; i += 256) {
                    int r = i >> 5, c4 = (i & 31) << 2;
                    *(float4*)(sW + r * 136 + c4) = *(const float4*)(tfWoe + (64 + r) * 128 + c4);
                }
                __syncthreads();
            }
#pragma unroll 2
            for (int k0 = 0; k0 < 64; k0 += 8) {
                int kk = half * 64 + k0;
                uint32_t a[2][4];
#pragma unroll
                for (int m = 0; m < 2; m++) {
                    int rr = wm * 32 + m * 16;
                    a[m][0] = __float_as_uint(sS[(rr + g) * 132 + kk + q]);
                    a[m][1] = __float_as_uint(sS[(rr + g + 8) * 132 + kk + q]);
                    a[m][2] = __float_as_uint(sS[(rr + g) * 132 + kk + q + 4]);
                    a[m][3] = __float_as_uint(sS[(rr + g + 8) * 132 + kk + q + 4]);
                }
#pragma unroll
                for (int n = 0; n < 4; n++) {
                    uint32_t b0 = __float_as_uint(sW[(k0 + q) * 136 + nc0 + n * 8 + g]);
                    uint32_t b1 = __float_as_uint(sW[(k0 + q + 4) * 136 + nc0 + n * 8 + g]);
                    mma8(c2[0][n], a[0], b0, b1);
                    mma8(c2[1][n], a[1], b0, b1);
                }
            }
        }
        __syncthreads();   // sE fully read (GEMM1 done long ago) and sW reads done
#pragma unroll
        for (int m = 0; m < 2; m++)
#pragma unroll
            for (int n = 0; n < 4; n++) {
                int r0 = wm * 32 + m * 16 + g, r1 = r0 + 8;
                int cc = nc0 + n * 8 + 2 * q;
                sO[r0 * 132 + cc] = c2[m][n][0];
                sO[r0 * 132 + cc + 1] = c2[m][n][1];
                sO[r1 * 132 + cc] = c2[m][n][2];
                sO[r1 * 132 + cc + 1] = c2[m][n][3];
            }
    }
    __syncthreads();

    // epilogue: bias + residual (re-read e fp32) + store + stats
    const int tx = tid & 15, ty = tid >> 4;
    float4 bb0 = *(const float4*)(bo_e + tx * 8);
    float4 bb1 = *(const float4*)(bo_e + tx * 8 + 4);
    float bias[8] = {bb0.x, bb0.y, bb0.z, bb0.w, bb1.x, bb1.y, bb1.z, bb1.w};
    float csum[8] = {0, 0, 0, 0, 0, 0, 0, 0};
    float csq[8] = {0, 0, 0, 0, 0, 0, 0, 0};
#pragma unroll
    for (int i = 0; i < 4; i++) {
        int r = ty * 4 + i;
        float4 e0 = *(const float4*)(e + (row0 + r) * D + tx * 8);
        float4 e1 = *(const float4*)(e + (row0 + r) * D + tx * 8 + 4);
        float ev[8] = {e0.x, e0.y, e0.z, e0.w, e1.x, e1.y, e1.z, e1.w};
        float o[8];
#pragma unroll
        for (int j = 0; j < 8; j++) {
            o[j] = sO[r * 132 + tx * 8 + j] + bias[j] + ev[j];
            csum[j] += o[j];
            csq[j] += o[j] * o[j];
        }
        *(float4*)(g_ee + (row0 + r) * 128 + tx * 8) = make_float4(o[0], o[1], o[2], o[3]);
        *(float4*)(g_ee + (row0 + r) * 128 + tx * 8 + 4) = make_float4(o[4], o[5], o[6], o[7]);
    }
#pragma unroll
    for (int j = 0; j < 8; j++) {
        atomicAdd(&sCS[tx * 8 + j], csum[j]);
        atomicAdd(&sCQ[tx * 8 + j], csq[j]);
    }
    __syncthreads();
    if (tid < 128) {
        atomicAdd(&g_stats[0 * 128 + tid], sCS[tid]);
        atomicAdd(&g_stats[1 * 128 + tid], sCQ[tid]);
    }
}

// ---------------- node attention output (tf32 mma, 2 CTAs/SM) ----------------
__global__ __launch_bounds__(256, 2) void k_nattn(const float* __restrict__ h,
                                                  const float* __restrict__ bo_h) {
    extern __shared__ float sm[];
    float* sA = sm;                 // 128 x 132 (tf32 h_attn); aliased by sO after mainloop
    float* sB = sA + 128 * 132;     // 64 x 136 (tf32 Wo_h k-chunk)
    float* sCS = sB + 64 * 136;     // 128
    float* sCQ = sCS + 128;         // 128
    float* sO = sA;                 // overlay
    const int tid = threadIdx.x;
    const int lane = tid & 31, wid = tid >> 5;
    const int g = lane >> 2, q = lane & 3;
    const int wm = wid >> 1, wn = wid & 1;
    const int tx = tid & 15, ty = tid >> 4;
    const int row0 = blockIdx.x * 128;

    for (int i = tid; i < 128 * 128; i += 256) {
        int r = i >> 7, c = i & 127;
        int gr = row0 + r;
        float v = 0.f;
        if (gr < NN) {
            float zz = g_z[gr * 8 + (c >> 4)];
            v = g_wV[gr * 128 + c] / (zz + 1e-6f);
        }
        sA[r * 132 + c] = f2tf_f(v);
    }
    if (tid < 128) { sCS[tid] = 0.f; sCQ[tid] = 0.f; }

    float acc[2][8][4];
#pragma unroll
    for (int m = 0; m < 2; m++)
#pragma unroll
        for (int n = 0; n < 8; n++)
#pragma unroll
            for (int j = 0; j < 4; j++) acc[m][n][j] = 0.f;

    for (int half = 0; half < 2; half++) {
        __syncthreads();
        for (int i = tid; i < 64 * 32; i += 256) {
            int r = i >> 5, c4 = (i & 31) << 2;
            *(float4*)(sB + r * 136 + c4) = *(const float4*)(g_tfw + TOH + (half * 64 + r) * 128 + c4);
        }
        __syncthreads();

#pragma unroll 2
        for (int k0 = 0; k0 < 64; k0 += 8) {
            int kk = half * 64 + k0;
            uint32_t a[2][4];
#pragma unroll
            for (int m = 0; m < 2; m++) {
                int rr = wm * 32 + m * 16;
                a[m][0] = __float_as_uint(sA[(rr + g) * 132 + kk + q]);
                a[m][1] = __float_as_uint(sA[(rr + g + 8) * 132 + kk + q]);
                a[m][2] = __float_as_uint(sA[(rr + g) * 132 + kk + q + 4]);
                a[m][3] = __float_as_uint(sA[(rr + g + 8) * 132 + kk + q + 4]);
            }
#pragma unroll
            for (int n = 0; n < 8; n++) {
                uint32_t b0 = __float_as_uint(sB[(k0 + q) * 136 + wn * 64 + n * 8 + g]);
                uint32_t b1 = __float_as_uint(sB[(k0 + q + 4) * 136 + wn * 64 + n * 8 + g]);
                mma8(acc[0][n], a[0], b0, b1);
                mma8(acc[1][n], a[1], b0, b1);
            }
        }
    }
    __syncthreads();   // all warps done reading sA before overlay writes

#pragma unroll
    for (int m = 0; m < 2; m++)
#pragma unroll
        for (int n = 0; n < 8; n++) {
            int r0 = wm * 32 + m * 16 + g, r1 = r0 + 8;
            int cc = wn * 64 + n * 8 + 2 * q;
            sO[r0 * 132 + cc] = acc[m][n][0];
            sO[r0 * 132 + cc + 1] = acc[m][n][1];
            sO[r1 * 132 + cc] = acc[m][n][2];
            sO[r1 * 132 + cc + 1] = acc[m][n][3];
        }
    __syncthreads();

    float4 bb0 = *(const float4*)(bo_h + tx * 8);
    float4 bb1 = *(const float4*)(bo_h + tx * 8 + 4);
    float bias[8] = {bb0.x, bb0.y, bb0.z, bb0.w, bb1.x, bb1.y, bb1.z, bb1.w};
    float csum[8] = {0, 0, 0, 0, 0, 0, 0, 0};
    float csq[8] = {0, 0, 0, 0, 0, 0, 0, 0};
#pragma unroll
    for (int i = 0; i < 8; i++) {
        int r = ty * 8 + i;
        int gr = row0 + r;
        if (gr < NN) {
            float4 r0 = *(const float4*)(h + gr * 128 + tx * 8);
            float4 r1 = *(const float4*)(h + gr * 128 + tx * 8 + 4);
            float hv[8] = {r0.x, r0.y, r0.z, r0.w, r1.x, r1.y, r1.z, r1.w};
            float o[8];
#pragma unroll
            for (int j = 0; j < 8; j++) {
                o[j] = sO[r * 132 + tx * 8 + j] + bias[j] + hv[j];
                csum[j] += o[j];
                csq[j] += o[j] * o[j];
            }
            *(float4*)(g_hh + gr * 128 + tx * 8) = make_float4(o[0], o[1], o[2], o[3]);
            *(float4*)(g_hh + gr * 128 + tx * 8 + 4) = make_float4(o[4], o[5], o[6], o[7]);
        }
    }
#pragma unroll
    for (int j = 0; j < 8; j++) {
        atomicAdd(&sCS[tx * 8 + j], csum[j]);
        atomicAdd(&sCQ[tx * 8 + j], csq[j]);
    }
    __syncthreads();
    if (tid < 128) {
        atomicAdd(&g_stats[2 * 128 + tid], sCS[tid]);
        atomicAdd(&g_stats[3 * 128 + tid], sCQ[tid]);
    }
}

// ---------------- finalize BN stats ----------------
__global__ void k_finalize(int statOff, float cnt, int bnOff) {
    int c = threadIdx.x;  // 128
    float m = g_stats[statOff + c] / cnt;
    float var = g_stats[statOff + 128 + c] / cnt - m * m;
    g_bnp[bnOff + c] = m;
    g_bnp[bnOff + 128 + c] = rsqrtf(var + 1e-5f);
}

// ---------------- k_ffn prefetch helper ----------------
__device__ __forceinline__ void ffn_prefetch(const float* W1t, const float* W2t,
                                             float* sW1buf, float* sW2buf, int ch, int tid) {
    uint32_t d1 = (uint32_t)__cvta_generic_to_shared(sW1buf);
#pragma unroll
    for (int j = 0; j < 4; j++) {
        int idx = tid + j * 256;
        int r = idx >> 3, c4 = (idx & 7) << 2;
        cpasync16(d1 + (uint32_t)(r * 40 + c4) * 4u, W1t + r * 256 + ch * 32 + c4);
    }
    uint32_t d2 = (uint32_t)__cvta_generic_to_shared(sW2buf);
#pragma unroll
    for (int j = 0; j < 4; j++) {
        int idx = tid + j * 256;
        int r = idx >> 5, c4 = (idx & 31) << 2;
        cpasync16(d2 + (uint32_t)(r * 136 + c4) * 4u, W2t + (ch * 32 + r) * 128 + c4);
    }
    asm volatile("cp.async.commit_group;" ::: "memory");
}

// ---------------- fused BN1 + FFN + residual + stats2 (tf32, cp.async double-buffered) ----------------
__global__ __launch_bounds__(256, 1) void k_ffn(const float* __restrict__ xin, float* xout,
                                                int bnOff,
                                                const float* __restrict__ gam,
                                                const float* __restrict__ bet,
                                                const float* __restrict__ W1t,   // tf32 128x256
                                                const float* __restrict__ ba,
                                                const float* __restrict__ W2t,   // tf32 256x128
                                                const float* __restrict__ bb2,
                                                int statOff, int nrows) {
    extern __shared__ float sm[];
    float* sX = sm;                      // 128x132 tf32 post-BN
    float* sW1 = sX + 128 * 132;         // 2 x 128x40
    float* sY = sW1 + 2 * 128 * 40;      // 128x36
    float* sW2 = sY + 128 * 36;          // 2 x 32x136
    float* sCS = sW2 + 2 * 32 * 136;     // 128
    float* sCQ = sCS + 128;              // 128
    float* sO = sW1;                     // overlay 128x132 (epilogue only)

    const int tid = threadIdx.x;
    const int lane = tid & 31, wid = tid >> 5;
    const int g = lane >> 2, q = lane & 3;
    const int wm = wid >> 1, wn = wid & 1;
    const int row0 = blockIdx.x * 128;
    const float* mean = g_bnp + bnOff;
    const float* istd = g_bnp + bnOff + 128;

    for (int i = tid; i < 128 * 128; i += 256) {
        int r = i >> 7, c = i & 127;
        int gr = row0 + r;
        float v = 0.f;
        if (gr < nrows) v = (xin[(size_t)gr * 128 + c] - mean[c]) * istd[c] * gam[c] + bet[c];
        sX[r * 132 + c] = f2tf_f(v);
    }
    if (tid < 128) { sCS[tid] = 0.f; sCQ[tid] = 0.f; }

    ffn_prefetch(W1t, W2t, sW1, sW2, 0, tid);
    ffn_prefetch(W1t, W2t, sW1 + 128 * 40, sW2 + 32 * 136, 1, tid);

    float accO[2][8][4];
#pragma unroll
    for (int m = 0; m < 2; m++)
#pragma unroll
        for (int n = 0; n < 8; n++)
#pragma unroll
            for (int j = 0; j < 4; j++) accO[m][n][j] = 0.f;

    for (int ch = 0; ch < 8; ch++) {
        int buf = ch & 1;
        if (ch < 7) { asm volatile("cp.async.wait_group 1;" ::: "memory"); }
        else        { asm volatile("cp.async.wait_group 0;" ::: "memory"); }
        __syncthreads();
        const float* w1 = sW1 + buf * 128 * 40;
        const float* w2 = sW2 + buf * 32 * 136;

        // GEMM1: y = relu(sX @ W1chunk + b1chunk)   out 128 x 32
        float c1[2][2][4];
#pragma unroll
        for (int m = 0; m < 2; m++)
#pragma unroll
            for (int n = 0; n < 2; n++)
#pragma unroll
                for (int j = 0; j < 4; j++) c1[m][n][j] = 0.f;

        const int cn = wn * 16;
#pragma unroll 2
        for (int k0 = 0; k0 < 128; k0 += 8) {
            uint32_t a[2][4];
#pragma unroll
            for (int m = 0; m < 2; m++) {
                int rr = wm * 32 + m * 16;
                a[m][0] = __float_as_uint(sX[(rr + g) * 132 + k0 + q]);
                a[m][1] = __float_as_uint(sX[(rr + g + 8) * 132 + k0 + q]);
                a[m][2] = __float_as_uint(sX[(rr + g) * 132 + k0 + q + 4]);
                a[m][3] = __float_as_uint(sX[(rr + g + 8) * 132 + k0 + q + 4]);
            }
#pragma unroll
            for (int n = 0; n < 2; n++) {
                uint32_t b0 = __float_as_uint(w1[(k0 + q) * 40 + cn + n * 8 + g]);
                uint32_t b1 = __float_as_uint(w1[(k0 + q + 4) * 40 + cn + n * 8 + g]);
                mma8(c1[0][n], a[0], b0, b1);
                mma8(c1[1][n], a[1], b0, b1);
            }
        }
#pragma unroll
        for (int m = 0; m < 2; m++)
#pragma unroll
            for (int n = 0; n < 2; n++) {
                int cc = cn + n * 8 + 2 * q;
                float bv0 = ba[ch * 32 + cc], bv1 = ba[ch * 32 + cc + 1];
                int r0 = wm * 32 + m * 16 + g, r1 = r0 + 8;
                sY[r0 * 36 + cc] = f2tf_f(fmaxf(c1[m][n][0] + bv0, 0.f));
                sY[r0 * 36 + cc + 1] = f2tf_f(fmaxf(c1[m][n][1] + bv1, 0.f));
                sY[r1 * 36 + cc] = f2tf_f(fmaxf(c1[m][n][2] + bv0, 0.f));
                sY[r1 * 36 + cc + 1] = f2tf_f(fmaxf(c1[m][n][3] + bv1, 0.f));
            }
        __syncthreads();

        // GEMM2 accumulate: out += y @ W2chunk   (k = 32)
#pragma unroll
        for (int k0 = 0; k0 < 32; k0 += 8) {
            uint32_t a[2][4];
#pragma unroll
            for (int m = 0; m < 2; m++) {
                int rr = wm * 32 + m * 16;
                a[m][0] = __float_as_uint(sY[(rr + g) * 36 + k0 + q]);
                a[m][1] = __float_as_uint(sY[(rr + g + 8) * 36 + k0 + q]);
                a[m][2] = __float_as_uint(sY[(rr + g) * 36 + k0 + q + 4]);
                a[m][3] = __float_as_uint(sY[(rr + g + 8) * 36 + k0 + q + 4]);
            }
#pragma unroll
            for (int n = 0; n < 8; n++) {
                uint32_t b0 = __float_as_uint(w2[(k0 + q) * 136 + wn * 64 + n * 8 + g]);
                uint32_t b1 = __float_as_uint(w2[(k0 + q + 4) * 136 + wn * 64 + n * 8 + g]);
                mma8(accO[0][n], a[0], b0, b1);
                mma8(accO[1][n], a[1], b0, b1);
            }
        }
        __syncthreads();
        if (ch + 2 < 8)
            ffn_prefetch(W1t, W2t, sW1 + buf * 128 * 40, sW2 + buf * 32 * 136, ch + 2, tid);
    }

    // stage output frags to sO (overlay; all cp.async retired, all reads done)
#pragma unroll
    for (int m = 0; m < 2; m++)
#pragma unroll
        for (int n = 0; n < 8; n++) {
            int r0 = wm * 32 + m * 16 + g, r1 = r0 + 8;
            int cc = wn * 64 + n * 8 + 2 * q;
            sO[r0 * 132 + cc] = accO[m][n][0];
            sO[r0 * 132 + cc + 1] = accO[m][n][1];
            sO[r1 * 132 + cc] = accO[m][n][2];
            sO[r1 * 132 + cc + 1] = accO[m][n][3];
        }
    __syncthreads();

    // epilogue: bias + residual (recompute BN fp32 from re-read xin) + store + stats
    const int tx = tid & 15, ty = tid >> 4;
    float4 c0 = *(const float4*)(bb2 + tx * 8);
    float4 c1v = *(const float4*)(bb2 + tx * 8 + 4);
    float bias[8] = {c0.x, c0.y, c0.z, c0.w, c1v.x, c1v.y, c1v.z, c1v.w};
    float mn[8], is_[8], gm[8], bt[8];
#pragma unroll
    for (int j = 0; j < 8; j++) {
        int c = tx * 8 + j;
        mn[j] = mean[c]; is_[j] = istd[c]; gm[j] = gam[c]; bt[j] = bet[c];
    }
    float csum[8] = {0, 0, 0, 0, 0, 0, 0, 0};
    float csq[8] = {0, 0, 0, 0, 0, 0, 0, 0};
#pragma unroll
    for (int i = 0; i < 8; i++) {
        int r = ty * 8 + i;
        int gr = row0 + r;
        if (gr < nrows) {
            float4 x0 = *(const float4*)(xin + (size_t)gr * 128 + tx * 8);
            float4 x1 = *(const float4*)(xin + (size_t)gr * 128 + tx * 8 + 4);
            float xv[8] = {x0.x, x0.y, x0.z, x0.w, x1.x, x1.y, x1.z, x1.w};
            float o[8];
#pragma unroll
            for (int j = 0; j < 8; j++) {
                float resid = (xv[j] - mn[j]) * is_[j] * gm[j] + bt[j];
                o[j] = sO[r * 132 + tx * 8 + j] + bias[j] + resid;
                csum[j] += o[j];
                csq[j] += o[j] * o[j];
            }
            *(float4*)(xout + (size_t)gr * 128 + tx * 8) = make_float4(o[0], o[1], o[2], o[3]);
            *(float4*)(xout + (size_t)gr * 128 + tx * 8 + 4) = make_float4(o[4], o[5], o[6], o[7]);
        }
    }
#pragma unroll
    for (int j = 0; j < 8; j++) {
        atomicAdd(&sCS[tx * 8 + j], csum[j]);
        atomicAdd(&sCQ[tx * 8 + j], csq[j]);
    }
    __syncthreads();
    if (tid < 128) {
        atomicAdd(&g_stats[statOff + tid], sCS[tid]);
        atomicAdd(&g_stats[statOff + 128 + tid], sCQ[tid]);
    }
}

// ---------------- final BN (elementwise) ----------------
__global__ void k_bnout(const float* x, int bnOff, const float* gam, const float* bet,
                        float* o, int nrows) {
    const float* mean = g_bnp + bnOff;
    const float* istd = g_bnp + bnOff + 128;
    int idx = blockIdx.x * blockDim.x + threadIdx.x;
    int stride = gridDim.x * blockDim.x;
    int total = nrows * 32;  // float4 units
    for (int i = idx; i < total; i += stride) {
        int c = (i & 31) << 2;
        float4 v = *(const float4*)(x + (size_t)i * 4);
        float4 r;
        r.x = (v.x - mean[c + 0]) * istd[c + 0] * gam[c + 0] + bet[c + 0];
        r.y = (v.y - mean[c + 1]) * istd[c + 1] * gam[c + 1] + bet[c + 1];
        r.z = (v.z - mean[c + 2]) * istd[c + 2] * gam[c + 2] + bet[c + 2];
        r.w = (v.w - mean[c + 3]) * istd[c + 3] * gam[c + 3] + bet[c + 3];
        *(float4*)(o + (size_t)i * 4) = r;
    }
}

// ---------------- launch ----------------
extern "C" void kernel_launch(void* const* d_in, const int* in_sizes, int n_in,
                              void* d_out, int out_size) {
    const float* h = (const float*)d_in[0];
    const float* e = (const float*)d_in[1];
    const int* src = (const int*)d_in[2];
    const int* dst = (const int*)d_in[3];
    const float* Wq = (const float*)d_in[4];
    const float* Wk = (const float*)d_in[5];
    const float* Wv = (const float*)d_in[6];
    const float* We = (const float*)d_in[7];
    const float* Wo_h = (const float*)d_in[8];
    const float* bo_h = (const float*)d_in[9];
    const float* Wo_e = (const float*)d_in[10];
    const float* bo_e = (const float*)d_in[11];
    const float* g1h = (const float*)d_in[12];
    const float* b1h = (const float*)d_in[13];
    const float* g1e = (const float*)d_in[14];
    const float* b1e = (const float*)d_in[15];
    const float* Wf1h = (const float*)d_in[16];
    const float* bf1h = (const float*)d_in[17];
    const float* Wf2h = (const float*)d_in[18];
    const float* bf2h = (const float*)d_in[19];
    const float* Wf1e = (const float*)d_in[20];
    const float* bf1e = (const float*)d_in[21];
    const float* Wf2e = (const float*)d_in[22];
    const float* bf2e = (const float*)d_in[23];
    const float* g2h = (const float*)d_in[24];
    const float* b2h = (const float*)d_in[25];
    const float* g2e = (const float*)d_in[26];
    const float* b2e = (const float*)d_in[27];
    float* out = (float*)d_out;
    float* out_e = out + (size_t)NN * D;

    float *p_hh, *p_h2, *p_ee, *p_tfw;
    cudaGetSymbolAddress((void**)&p_hh, g_hh);
    cudaGetSymbolAddress((void**)&p_h2, g_h2);
    cudaGetSymbolAddress((void**)&p_ee, g_ee);
    cudaGetSymbolAddress((void**)&p_tfw, g_tfw);

    const int smQ = (128 * 132 + 64 * 136) * 4;                              // ~100KB
    const int smN = (128 * 132 + 64 * 136 + 256) * 4;                        // ~101KB
    const int sm1 = (64 * 132 * 2 + 64 * 136 + 512 + 256 + 128) * 4;         // ~106KB
    const int smF = (128 * 132 + 2 * 128 * 40 + 128 * 36 + 2 * 32 * 136 + 256) * 4;
    cudaFuncSetAttribute(k_qkv, cudaFuncAttributeMaxDynamicSharedMemorySize, smQ);
    cudaFuncSetAttribute(k_nattn, cudaFuncAttributeMaxDynamicSharedMemorySize, smN);
    cudaFuncSetAttribute(k_edge1, cudaFuncAttributeMaxDynamicSharedMemorySize, sm1);
    cudaFuncSetAttribute(k_ffn, cudaFuncAttributeMaxDynamicSharedMemorySize, smF);

    const int NBLK = (NN + 127) / 128;  // 391

    k_zero<<<2048, 256>>>();
    k_prep<<<256, 256>>>(Wq, Wk, Wv, We, Wo_h, Wo_e, Wf1h, Wf2h, Wf1e, Wf2e);
    k_qkv<<<NBLK, 256, smQ>>>(h);
    k_edge1<<<NE / 64, 256, sm1>>>(e, src, dst, bo_e);
    k_nattn<<<NBLK, 256, smN>>>(h, bo_h);
    k_finalize<<<1, 128>>>(0, (float)NE, 0);      // bn1e
    k_finalize<<<1, 128>>>(256, (float)NN, 256);  // bn1h
    k_ffn<<<NE / 128, 256, smF>>>(p_ee, out_e, 0, g1e, b1e, p_tfw + T1E, bf1e, p_tfw + T2E, bf2e, 512, NE);
    k_ffn<<<NBLK, 256, smF>>>(p_hh, p_h2, 256, g1h, b1h, p_tfw + T1H, bf1h, p_tfw + T2H, bf2h, 768, NN);
    k_finalize<<<1, 128>>>(512, (float)NE, 512);  // bn2e
    k_finalize<<<1, 128>>>(768, (float)NN, 768);  // bn2h
    k_bnout<<<2960, 256>>>(p_h2, 768, g2h, b2h, out, NN);
    k_bnout<<<2960, 256>>>(out_e, 512, g2e, b2e, out_e, NE);
}